// round 3
// baseline (speedup 1.0000x reference)
#include <cuda_runtime.h>
#include <cuda_bf16.h>
#include <math.h>
#include <stdint.h>

#define S_LEN 2048
#define EMB   2048
#define NHEAD 16
#define HDIM  128

// ---------------- scratch (no cudaMalloc allowed) ----------------
__device__ float g_q [S_LEN * EMB];
__device__ float g_k [S_LEN * EMB];
__device__ float g_v [S_LEN * EMB];
__device__ float g_ao[S_LEN * EMB];

__device__ __nv_bfloat16 g_x_hi [S_LEN * EMB];
__device__ __nv_bfloat16 g_x_lo [S_LEN * EMB];
__device__ __nv_bfloat16 g_wq_hi[EMB * EMB];
__device__ __nv_bfloat16 g_wq_lo[EMB * EMB];
__device__ __nv_bfloat16 g_wk_hi[EMB * EMB];
__device__ __nv_bfloat16 g_wk_lo[EMB * EMB];
__device__ __nv_bfloat16 g_wv_hi[EMB * EMB];
__device__ __nv_bfloat16 g_wv_lo[EMB * EMB];
__device__ __nv_bfloat16 g_wo_hi[EMB * EMB];
__device__ __nv_bfloat16 g_wo_lo[EMB * EMB];
__device__ __nv_bfloat16 g_ao_hi[S_LEN * EMB];
__device__ __nv_bfloat16 g_ao_lo[S_LEN * EMB];

// ================= helpers (baseline PTX only: sm_80-level) ==============
__device__ __forceinline__ uint32_t s2u(const void* p) {
    uint32_t a;
    asm("{ .reg .u64 t; cvta.to.shared.u64 t, %1; cvt.u32.u64 %0, t; }"
        : "=r"(a) : "l"(p));
    return a;
}

__device__ __forceinline__ void cpa16(uint32_t dst, const void* src) {
    asm volatile("cp.async.cg.shared.global [%0], [%1], 16;" :: "r"(dst), "l"(src));
}
#define CPA_COMMIT() asm volatile("cp.async.commit_group;" ::: "memory")
#define CPA_WAIT1()  asm volatile("cp.async.wait_group 1;" ::: "memory")

__device__ __forceinline__ void ldsm4(uint32_t addr, uint32_t& r0, uint32_t& r1,
                                      uint32_t& r2, uint32_t& r3) {
    asm volatile("ldmatrix.sync.aligned.m8n8.x4.shared.b16 {%0,%1,%2,%3}, [%4];"
                 : "=r"(r0), "=r"(r1), "=r"(r2), "=r"(r3) : "r"(addr));
}

__device__ __forceinline__ void mma_bf16(float* d, const uint32_t* a,
                                         uint32_t b0, uint32_t b1) {
    asm volatile(
        "mma.sync.aligned.m16n8k16.row.col.f32.bf16.bf16.f32 "
        "{%0,%1,%2,%3}, {%4,%5,%6,%7}, {%8,%9}, {%0,%1,%2,%3};"
        : "+f"(d[0]), "+f"(d[1]), "+f"(d[2]), "+f"(d[3])
        : "r"(a[0]), "r"(a[1]), "r"(a[2]), "r"(a[3]), "r"(b0), "r"(b1));
}

// ================= split fp32 -> bf16 hi/lo ==============================
__global__ __launch_bounds__(256) void split_kernel(
    const float* __restrict__ src, __nv_bfloat16* __restrict__ hi,
    __nv_bfloat16* __restrict__ lo, int n)
{
    int i = (blockIdx.x * 256 + threadIdx.x) * 4;
    if (i >= n) return;
    float4 v = *(const float4*)(src + i);
    __nv_bfloat16 h0 = __float2bfloat16(v.x);
    __nv_bfloat16 h1 = __float2bfloat16(v.y);
    __nv_bfloat16 h2 = __float2bfloat16(v.z);
    __nv_bfloat16 h3 = __float2bfloat16(v.w);
    __nv_bfloat16 l0 = __float2bfloat16(v.x - __bfloat162float(h0));
    __nv_bfloat16 l1 = __float2bfloat16(v.y - __bfloat162float(h1));
    __nv_bfloat16 l2 = __float2bfloat16(v.z - __bfloat162float(h2));
    __nv_bfloat16 l3 = __float2bfloat16(v.w - __bfloat162float(h3));
    *(__nv_bfloat162*)(hi + i)     = __nv_bfloat162(h0, h1);
    *(__nv_bfloat162*)(hi + i + 2) = __nv_bfloat162(h2, h3);
    *(__nv_bfloat162*)(lo + i)     = __nv_bfloat162(l0, l1);
    *(__nv_bfloat162*)(lo + i + 2) = __nv_bfloat162(l2, l3);
}

// ================= mma.sync GEMM: C[2048,2048] = A * B^T (bf16x3) =========
// CTA tile 128x128, 8 warps (4x2), warp tile 32x64. K staged 16/chunk.
// smem per buffer: Ah,Al,Bh,Bl each 128 rows x 48B (16 bf16 + pad) = 6144B.
#define ROWB      48
#define ARR_B     (128 * ROWB)       // 6144
#define BUF_B     (4 * ARR_B)        // 24576
#define GM_SMEM   (2 * BUF_B)        // 49152

__global__ __launch_bounds__(256, 2) void gemm_mma(
    const __nv_bfloat16* __restrict__ Ah, const __nv_bfloat16* __restrict__ Al,
    const __nv_bfloat16* __restrict__ Bh, const __nv_bfloat16* __restrict__ Bl,
    float* __restrict__ C)
{
    extern __shared__ char smraw[];
    const uint32_t sbase = s2u(smraw);

    const int tid  = threadIdx.x;
    const int lane = tid & 31;
    const int wid  = tid >> 5;
    const int wm   = wid & 3;        // warp row (0..3) -> rows wm*32
    const int wn   = wid >> 2;       // warp col (0..1) -> cols wn*64
    const int bm   = blockIdx.y * 128;
    const int bn   = blockIdx.x * 128;

    // global load mapping: each thread does 4 cp.async of 16B per chunk
    const int e_row = tid >> 1;      // 0..127
    const int e_chk = tid & 1;       // 16B chunk within 32B row
    const __nv_bfloat16* gA[2] = {Ah + (size_t)(bm + e_row) * EMB + e_chk * 8,
                                  Al + (size_t)(bm + e_row) * EMB + e_chk * 8};
    const __nv_bfloat16* gB[2] = {Bh + (size_t)(bn + e_row) * EMB + e_chk * 8,
                                  Bl + (size_t)(bn + e_row) * EMB + e_chk * 8};
    const uint32_t sdst = e_row * ROWB + e_chk * 16;

    // ldmatrix per-lane offsets
    const int l   = lane & 7;
    const int mtx = lane >> 3;       // matrix index 0..3 within x4
    uint32_t offA[2], offB[4];
#pragma unroll
    for (int i = 0; i < 2; i++)
        offA[i] = (uint32_t)((wm * 32 + i * 16 + (mtx & 1) * 8 + l) * ROWB + (mtx >> 1) * 16);
#pragma unroll
    for (int j = 0; j < 4; j++)
        offB[j] = (uint32_t)((wn * 64 + j * 16 + (mtx >> 1) * 8 + l) * ROWB + (mtx & 1) * 16);

    float acc[2][8][4];
#pragma unroll
    for (int i = 0; i < 2; i++)
#pragma unroll
        for (int j = 0; j < 8; j++)
#pragma unroll
            for (int t = 0; t < 4; t++) acc[i][j][t] = 0.f;

    const int NCH = EMB / 16;        // 128 chunks

    // prologue: chunk 0 -> buf 0
    {
        uint32_t bb = sbase;
        cpa16(bb + 0 * ARR_B + sdst, gA[0]);
        cpa16(bb + 1 * ARR_B + sdst, gA[1]);
        cpa16(bb + 2 * ARR_B + sdst, gB[0]);
        cpa16(bb + 3 * ARR_B + sdst, gB[1]);
    }
    CPA_COMMIT();

    for (int s = 0; s < NCH; s++) {
        if (s + 1 < NCH) {
            uint32_t bb = sbase + ((s + 1) & 1) * BUF_B;
            int koff = (s + 1) * 16;
            cpa16(bb + 0 * ARR_B + sdst, gA[0] + koff);
            cpa16(bb + 1 * ARR_B + sdst, gA[1] + koff);
            cpa16(bb + 2 * ARR_B + sdst, gB[0] + koff);
            cpa16(bb + 3 * ARR_B + sdst, gB[1] + koff);
        }
        CPA_COMMIT();
        CPA_WAIT1();            // chunk s resident
        __syncthreads();

        const uint32_t bb = sbase + (s & 1) * BUF_B;
#pragma unroll
        for (int pass = 0; pass < 3; pass++) {
            const uint32_t abase = bb + (pass == 2 ? ARR_B : 0);
            const uint32_t bbase = bb + 2 * ARR_B + (pass == 1 ? ARR_B : 0);

            uint32_t a[2][4];
#pragma unroll
            for (int i = 0; i < 2; i++)
                ldsm4(abase + offA[i], a[i][0], a[i][1], a[i][2], a[i][3]);
            uint32_t b[4][4];
#pragma unroll
            for (int j = 0; j < 4; j++)
                ldsm4(bbase + offB[j], b[j][0], b[j][1], b[j][2], b[j][3]);

#pragma unroll
            for (int i = 0; i < 2; i++)
#pragma unroll
                for (int j = 0; j < 4; j++) {
                    mma_bf16(acc[i][j * 2 + 0], a[i], b[j][0], b[j][1]);
                    mma_bf16(acc[i][j * 2 + 1], a[i], b[j][2], b[j][3]);
                }
        }
        __syncthreads();        // before buf (s&1) is overwritten at s+2's issue
    }

    // epilogue
    const int g = lane >> 2;
    const int q = (lane & 3) * 2;
#pragma unroll
    for (int i = 0; i < 2; i++) {
#pragma unroll
        for (int j = 0; j < 8; j++) {
            int row = bm + wm * 32 + i * 16 + g;
            int col = bn + wn * 64 + j * 8 + q;
            *(float2*)(C + (size_t)row * EMB + col) =
                make_float2(acc[i][j][0], acc[i][j][1]);
            *(float2*)(C + (size_t)(row + 8) * EMB + col) =
                make_float2(acc[i][j][2], acc[i][j][3]);
        }
    }
}

// ---------------- RoPE (in-place on q and k; q also scaled 1/sqrt(d)) -----
__global__ __launch_bounds__(256) void rope_kernel(
    float* __restrict__ q, float* __restrict__ k,
    const float* __restrict__ cosb, const float* __restrict__ sinb)
{
    int idx = blockIdx.x * blockDim.x + threadIdx.x;
    const int total = S_LEN * NHEAD * (HDIM / 2);
    if (idx >= total) return;
    int d2 = idx & 63;
    int h  = (idx >> 6) & (NHEAD - 1);
    int s  = idx >> 10;

    float c1 = cosb[s * HDIM + d2];
    float s1 = sinb[s * HDIM + d2];
    float c2 = cosb[s * HDIM + 64 + d2];
    float s2 = sinb[s * HDIM + 64 + d2];

    const float scale = 0.088388347648318447f;  // 1/sqrt(128)
    size_t base = (size_t)s * EMB + h * HDIM;

    float q1 = q[base + d2], q2 = q[base + 64 + d2];
    q[base + d2]      = (q1 * c1 - q2 * s1) * scale;
    q[base + 64 + d2] = (q2 * c2 + q1 * s2) * scale;

    float k1 = k[base + d2], k2 = k[base + 64 + d2];
    k[base + d2]      = k1 * c1 - k2 * s1;
    k[base + 64 + d2] = k2 * c2 + k1 * s2;
}

// ---------------- Flash attention (causal, fp32) ----------------
#define FL_SMEM_FLOATS (2 * 128 * 68 + 64 * 128 + 64 * 68 + 3 * 64)
#define FL_SMEM_BYTES  (FL_SMEM_FLOATS * 4)

__global__ __launch_bounds__(256) void flash_attn(
    const float* __restrict__ q, const float* __restrict__ k,
    const float* __restrict__ v, float* __restrict__ o)
{
    const int ib = blockIdx.x;    // q block: rows ib*64 ..
    const int h  = blockIdx.y;

    extern __shared__ __align__(16) float sm[];
    float* Qs = sm;                   // [128][68]  Qs[d][r]
    float* Ks = Qs + 128 * 68;        // [128][68]  Ks[d][r]
    float* Vs = Ks + 128 * 68;        // [64][128]  row-major
    float* Ss = Vs + 64 * 128;        // [64][68]
    float* ms = Ss + 64 * 68;
    float* ls = ms + 64;
    float* al = ls + 64;

    const int tid  = threadIdx.x;
    const int lane = tid & 31;
    const int w    = tid >> 5;
    const int tx   = tid & 15;
    const int ty   = tid >> 4;

    const int lr = (lane >> 2) + 8 * w;   // 0..63 (row within tile)
    const int lc = lane & 3;              // d-group base

    {
        const float* qrow = q + (size_t)(ib * 64 + lr) * EMB + h * HDIM;
#pragma unroll
        for (int it = 0; it < 8; it++) {
            int c4 = lc + 4 * it;
            float4 vq = *(const float4*)(qrow + c4 * 4);
            Qs[(c4 * 4 + 0) * 68 + lr] = vq.x;
            Qs[(c4 * 4 + 1) * 68 + lr] = vq.y;
            Qs[(c4 * 4 + 2) * 68 + lr] = vq.z;
            Qs[(c4 * 4 + 3) * 68 + lr] = vq.w;
        }
    }
    if (tid < 64) { ms[tid] = -1e30f; ls[tid] = 0.f; }

    float acc_o[4][8];
#pragma unroll
    for (int i = 0; i < 4; i++)
#pragma unroll
        for (int j = 0; j < 8; j++) acc_o[i][j] = 0.f;

    __syncthreads();

    for (int jb = 0; jb <= ib; jb++) {
        {
            const float* krow = k + (size_t)(jb * 64 + lr) * EMB + h * HDIM;
#pragma unroll
            for (int it = 0; it < 8; it++) {
                int c4 = lc + 4 * it;
                float4 vk = *(const float4*)(krow + c4 * 4);
                Ks[(c4 * 4 + 0) * 68 + lr] = vk.x;
                Ks[(c4 * 4 + 1) * 68 + lr] = vk.y;
                Ks[(c4 * 4 + 2) * 68 + lr] = vk.z;
                Ks[(c4 * 4 + 3) * 68 + lr] = vk.w;
            }
#pragma unroll
            for (int it = 0; it < 8; it++) {
                int i = tid + it * 256;
                int r = i >> 5, c4 = i & 31;
                *(float4*)(Vs + r * 128 + c4 * 4) =
                    *(const float4*)(v + (size_t)(jb * 64 + r) * EMB + h * HDIM + c4 * 4);
            }
        }
        __syncthreads();

        float s[4][4];
#pragma unroll
        for (int i = 0; i < 4; i++)
#pragma unroll
            for (int j = 0; j < 4; j++) s[i][j] = 0.f;

#pragma unroll 4
        for (int kk = 0; kk < 128; kk++) {
            float a[4], b[4];
            *(float4*)a = *(const float4*)(Qs + kk * 68 + ty * 4);
            *(float4*)b = *(const float4*)(Ks + kk * 68 + tx * 4);
#pragma unroll
            for (int i = 0; i < 4; i++)
#pragma unroll
                for (int j = 0; j < 4; j++)
                    s[i][j] = fmaf(a[i], b[j], s[i][j]);
        }

        const bool diag = (jb == ib);
#pragma unroll
        for (int i = 0; i < 4; i++) {
            int row = ty * 4 + i;
#pragma unroll
            for (int j = 0; j < 4; j++) {
                int col = tx * 4 + j;
                if (diag && col > row) s[i][j] = -1e30f;
            }
            float4 sv = make_float4(s[i][0], s[i][1], s[i][2], s[i][3]);
            *(float4*)(Ss + row * 68 + tx * 4) = sv;
        }
        __syncthreads();

        if (tid < 64) {
            float m_old = ms[tid];
            float mx = m_old;
#pragma unroll 8
            for (int j = 0; j < 64; j++) mx = fmaxf(mx, Ss[tid * 68 + j]);
            float alpha = __expf(m_old - mx);
            float sum = 0.f;
#pragma unroll 8
            for (int j = 0; j < 64; j++) {
                float p = __expf(Ss[tid * 68 + j] - mx);
                Ss[tid * 68 + j] = p;
                sum += p;
            }
            ms[tid] = mx;
            ls[tid] = ls[tid] * alpha + sum;
            al[tid] = alpha;
        }
        __syncthreads();

        float alpha_r[4];
#pragma unroll
        for (int i = 0; i < 4; i++) alpha_r[i] = al[ty * 4 + i];
#pragma unroll
        for (int i = 0; i < 4; i++)
#pragma unroll
            for (int j = 0; j < 8; j++) acc_o[i][j] *= alpha_r[i];

#pragma unroll 4
        for (int kk = 0; kk < 64; kk++) {
            float p[4], vv[8];
#pragma unroll
            for (int i = 0; i < 4; i++) p[i] = Ss[(ty * 4 + i) * 68 + kk];
            *(float4*)(vv)     = *(const float4*)(Vs + kk * 128 + tx * 4);
            *(float4*)(vv + 4) = *(const float4*)(Vs + kk * 128 + 64 + tx * 4);
#pragma unroll
            for (int i = 0; i < 4; i++)
#pragma unroll
                for (int j = 0; j < 8; j++)
                    acc_o[i][j] = fmaf(p[i], vv[j], acc_o[i][j]);
        }
        __syncthreads();
    }

#pragma unroll
    for (int i = 0; i < 4; i++) {
        int row = ty * 4 + i;
        float inv = 1.f / ls[row];
        size_t gbase = (size_t)(ib * 64 + row) * EMB + h * HDIM;
        float4 o0 = make_float4(acc_o[i][0] * inv, acc_o[i][1] * inv,
                                acc_o[i][2] * inv, acc_o[i][3] * inv);
        float4 o1 = make_float4(acc_o[i][4] * inv, acc_o[i][5] * inv,
                                acc_o[i][6] * inv, acc_o[i][7] * inv);
        *(float4*)(o + gbase + tx * 4)      = o0;
        *(float4*)(o + gbase + 64 + tx * 4) = o1;
    }
}

// ---------------- launch ----------------
extern "C" void kernel_launch(void* const* d_in, const int* in_sizes, int n_in,
                              void* d_out, int out_size)
{
    const float* x  = (const float*)d_in[0];
    const float* rc = (const float*)d_in[1];
    const float* rs = (const float*)d_in[2];
    const float* Wq = (const float*)d_in[3];
    const float* Wk = (const float*)d_in[4];
    const float* Wv = (const float*)d_in[5];
    const float* Wo = (const float*)d_in[6];
    float* out = (float*)d_out;

    float *q, *k, *v, *ao;
    cudaGetSymbolAddress((void**)&q,  g_q);
    cudaGetSymbolAddress((void**)&k,  g_k);
    cudaGetSymbolAddress((void**)&v,  g_v);
    cudaGetSymbolAddress((void**)&ao, g_ao);

    __nv_bfloat16 *xh, *xl, *qh, *ql, *kh, *kl, *vh, *vl, *oh, *ol, *aoh, *aol;
    cudaGetSymbolAddress((void**)&xh,  g_x_hi);
    cudaGetSymbolAddress((void**)&xl,  g_x_lo);
    cudaGetSymbolAddress((void**)&qh,  g_wq_hi);
    cudaGetSymbolAddress((void**)&ql,  g_wq_lo);
    cudaGetSymbolAddress((void**)&kh,  g_wk_hi);
    cudaGetSymbolAddress((void**)&kl,  g_wk_lo);
    cudaGetSymbolAddress((void**)&vh,  g_wv_hi);
    cudaGetSymbolAddress((void**)&vl,  g_wv_lo);
    cudaGetSymbolAddress((void**)&oh,  g_wo_hi);
    cudaGetSymbolAddress((void**)&ol,  g_wo_lo);
    cudaGetSymbolAddress((void**)&aoh, g_ao_hi);
    cudaGetSymbolAddress((void**)&aol, g_ao_lo);

    cudaFuncSetAttribute(flash_attn,
                         cudaFuncAttributeMaxDynamicSharedMemorySize, FL_SMEM_BYTES);
    cudaFuncSetAttribute(gemm_mma,
                         cudaFuncAttributeMaxDynamicSharedMemorySize, GM_SMEM);

    const int n = EMB * EMB;
    const int sb = (n / 4 + 255) / 256;

    split_kernel<<<sb, 256>>>(x,  xh, xl, n);
    split_kernel<<<sb, 256>>>(Wq, qh, ql, n);
    split_kernel<<<sb, 256>>>(Wk, kh, kl, n);
    split_kernel<<<sb, 256>>>(Wv, vh, vl, n);
    split_kernel<<<sb, 256>>>(Wo, oh, ol, n);

    dim3 gg(EMB / 128, S_LEN / 128);   // (16, 16) = 256 CTAs
    gemm_mma<<<gg, 256, GM_SMEM>>>(xh, xl, qh, ql, q);
    gemm_mma<<<gg, 256, GM_SMEM>>>(xh, xl, kh, kl, k);
    gemm_mma<<<gg, 256, GM_SMEM>>>(xh, xl, vh, vl, v);

    int rope_n = S_LEN * NHEAD * (HDIM / 2);
    rope_kernel<<<(rope_n + 255) / 256, 256>>>(q, k, rc, rs);

    flash_attn<<<dim3(S_LEN / 64, NHEAD), 256, FL_SMEM_BYTES>>>(q, k, v, ao);

    split_kernel<<<sb, 256>>>(ao, aoh, aol, n);
    gemm_mma<<<gg, 256, GM_SMEM>>>(aoh, aol, oh, ol, out);
}

// round 4
// speedup vs baseline: 1.5130x; 1.5130x over previous
#include <cuda_runtime.h>
#include <cuda_bf16.h>
#include <math.h>
#include <stdint.h>

#define S_LEN 2048
#define EMB   2048
#define NHEAD 16
#define HDIM  128

// ---------------- scratch (no cudaMalloc allowed) ----------------
__device__ float g_q [S_LEN * EMB];
__device__ float g_k [S_LEN * EMB];
__device__ float g_v [S_LEN * EMB];
__device__ float g_ao[S_LEN * EMB];

__device__ __nv_bfloat16 g_x_hi [S_LEN * EMB];
__device__ __nv_bfloat16 g_x_lo [S_LEN * EMB];
__device__ __nv_bfloat16 g_wq_hi[EMB * EMB];
__device__ __nv_bfloat16 g_wq_lo[EMB * EMB];
__device__ __nv_bfloat16 g_wk_hi[EMB * EMB];
__device__ __nv_bfloat16 g_wk_lo[EMB * EMB];
__device__ __nv_bfloat16 g_wv_hi[EMB * EMB];
__device__ __nv_bfloat16 g_wv_lo[EMB * EMB];
__device__ __nv_bfloat16 g_wo_hi[EMB * EMB];
__device__ __nv_bfloat16 g_wo_lo[EMB * EMB];
__device__ __nv_bfloat16 g_ao_hi[S_LEN * EMB];
__device__ __nv_bfloat16 g_ao_lo[S_LEN * EMB];

// ================= helpers (baseline PTX only: sm_80-level) ==============
__device__ __forceinline__ uint32_t s2u(const void* p) {
    uint32_t a;
    asm("{ .reg .u64 t; cvta.to.shared.u64 t, %1; cvt.u32.u64 %0, t; }"
        : "=r"(a) : "l"(p));
    return a;
}

__device__ __forceinline__ void cpa16(uint32_t dst, const void* src) {
    asm volatile("cp.async.cg.shared.global [%0], [%1], 16;" :: "r"(dst), "l"(src));
}
#define CPA_COMMIT() asm volatile("cp.async.commit_group;" ::: "memory")
#define CPA_WAIT1()  asm volatile("cp.async.wait_group 1;" ::: "memory")

__device__ __forceinline__ void ldsm4(uint32_t addr, uint32_t& r0, uint32_t& r1,
                                      uint32_t& r2, uint32_t& r3) {
    asm volatile("ldmatrix.sync.aligned.m8n8.x4.shared.b16 {%0,%1,%2,%3}, [%4];"
                 : "=r"(r0), "=r"(r1), "=r"(r2), "=r"(r3) : "r"(addr));
}

__device__ __forceinline__ void mma_bf16(float* d, const uint32_t* a,
                                         uint32_t b0, uint32_t b1) {
    asm volatile(
        "mma.sync.aligned.m16n8k16.row.col.f32.bf16.bf16.f32 "
        "{%0,%1,%2,%3}, {%4,%5,%6,%7}, {%8,%9}, {%0,%1,%2,%3};"
        : "+f"(d[0]), "+f"(d[1]), "+f"(d[2]), "+f"(d[3])
        : "r"(a[0]), "r"(a[1]), "r"(a[2]), "r"(a[3]), "r"(b0), "r"(b1));
}

// ================= split fp32 -> bf16 hi/lo ==============================
__global__ __launch_bounds__(256) void split_kernel(
    const float* __restrict__ src, __nv_bfloat16* __restrict__ hi,
    __nv_bfloat16* __restrict__ lo, int n)
{
    int i = (blockIdx.x * 256 + threadIdx.x) * 4;
    if (i >= n) return;
    float4 v = *(const float4*)(src + i);
    __nv_bfloat16 h0 = __float2bfloat16(v.x);
    __nv_bfloat16 h1 = __float2bfloat16(v.y);
    __nv_bfloat16 h2 = __float2bfloat16(v.z);
    __nv_bfloat16 h3 = __float2bfloat16(v.w);
    __nv_bfloat16 l0 = __float2bfloat16(v.x - __bfloat162float(h0));
    __nv_bfloat16 l1 = __float2bfloat16(v.y - __bfloat162float(h1));
    __nv_bfloat16 l2 = __float2bfloat16(v.z - __bfloat162float(h2));
    __nv_bfloat16 l3 = __float2bfloat16(v.w - __bfloat162float(h3));
    *(__nv_bfloat162*)(hi + i)     = __nv_bfloat162(h0, h1);
    *(__nv_bfloat162*)(hi + i + 2) = __nv_bfloat162(h2, h3);
    *(__nv_bfloat162*)(lo + i)     = __nv_bfloat162(l0, l1);
    *(__nv_bfloat162*)(lo + i + 2) = __nv_bfloat162(l2, l3);
}

// ================= mma.sync GEMM: C[2048,2048] = A * B^T (bf16x3) =========
// CTA tile 128x256, 16 warps (4x4), warp tile 32x64. K staged 64 per stage.
// smem rows padded to 144B (conflict-free ldmatrix + cp.async).
#define ROWB     144
#define A_PL     18432           // 128 * 144
#define B_PL     36864           // 256 * 144
#define STAGE_B  110592          // 2*A_PL + 2*B_PL
#define GM_SMEM  221184          // 2 stages

__global__ __launch_bounds__(512, 1) void gemm_mma(
    const __nv_bfloat16* __restrict__ Ah, const __nv_bfloat16* __restrict__ Al,
    const __nv_bfloat16* __restrict__ Bh, const __nv_bfloat16* __restrict__ Bl,
    float* __restrict__ C)
{
    extern __shared__ char smraw[];
    const uint32_t sbase = s2u(smraw);

    const int tid  = threadIdx.x;
    const int lane = tid & 31;
    const int wid  = tid >> 5;
    const int wm   = wid & 3;        // warp row -> rows wm*32
    const int wn   = wid >> 2;       // warp col (0..3) -> cols wn*64
    const int bm   = blockIdx.y * 128;
    const int bn   = blockIdx.x * 256;

    // ldmatrix per-lane offsets (proven mapping from round 3)
    const int l   = lane & 7;
    const int mtx = lane >> 3;
    uint32_t offA[2], offB[4];
#pragma unroll
    for (int i = 0; i < 2; i++)
        offA[i] = (uint32_t)((wm * 32 + i * 16 + (mtx & 1) * 8 + l) * ROWB + (mtx >> 1) * 16);
#pragma unroll
    for (int j = 0; j < 4; j++)
        offB[j] = (uint32_t)((wn * 64 + j * 16 + (mtx >> 1) * 8 + l) * ROWB + (mtx & 1) * 16);

    float acc[2][8][4];
#pragma unroll
    for (int i = 0; i < 2; i++)
#pragma unroll
        for (int j = 0; j < 8; j++)
#pragma unroll
            for (int t = 0; t < 4; t++) acc[i][j][t] = 0.f;

    const int NST = EMB / 64;    // 32 stages

    // ---- stage loader: fully coalesced (8 lanes cover one 128B row) ----
    auto load_stage = [&](uint32_t bb, int k0) {
#pragma unroll
        for (int i = 0; i < 4; i++) {          // A: 2 planes x 1024 ops
            int e = tid + i * 512;
            int p = e >> 10;
            int r = (e >> 3) & 127;
            int c = e & 7;
            const __nv_bfloat16* s = (p ? Al : Ah) + (size_t)(bm + r) * EMB + k0 + c * 8;
            cpa16(bb + p * A_PL + r * ROWB + c * 16, s);
        }
#pragma unroll
        for (int i = 0; i < 8; i++) {          // B: 2 planes x 2048 ops
            int e = tid + i * 512;
            int p = e >> 11;
            int r = (e >> 3) & 255;
            int c = e & 7;
            const __nv_bfloat16* s = (p ? Bl : Bh) + (size_t)(bn + r) * EMB + k0 + c * 8;
            cpa16(bb + 2 * A_PL + p * B_PL + r * ROWB + c * 16, s);
        }
    };

    // prologue: stage 0 -> buf 0
    load_stage(sbase, 0);
    CPA_COMMIT();

    for (int s = 0; s < NST; s++) {
        if (s + 1 < NST)
            load_stage(sbase + ((s + 1) & 1) * STAGE_B, (s + 1) * 64);
        CPA_COMMIT();
        CPA_WAIT1();            // stage s resident, s+1 in flight
        __syncthreads();

        const uint32_t bb = sbase + (s & 1) * STAGE_B;
#pragma unroll
        for (int pass = 0; pass < 3; pass++) {
            const uint32_t abase = bb + (pass == 2 ? A_PL : 0);
            const uint32_t bbase = bb + 2 * A_PL + (pass == 1 ? B_PL : 0);
#pragma unroll
            for (int ks = 0; ks < 4; ks++) {
                uint32_t a[2][4];
#pragma unroll
                for (int i = 0; i < 2; i++)
                    ldsm4(abase + offA[i] + ks * 32, a[i][0], a[i][1], a[i][2], a[i][3]);
                uint32_t b[4][4];
#pragma unroll
                for (int j = 0; j < 4; j++)
                    ldsm4(bbase + offB[j] + ks * 32, b[j][0], b[j][1], b[j][2], b[j][3]);
#pragma unroll
                for (int i = 0; i < 2; i++)
#pragma unroll
                    for (int j = 0; j < 4; j++) {
                        mma_bf16(acc[i][j * 2 + 0], a[i], b[j][0], b[j][1]);
                        mma_bf16(acc[i][j * 2 + 1], a[i], b[j][2], b[j][3]);
                    }
            }
        }
        __syncthreads();        // all warps done before buf is overwritten
    }

    // epilogue
    const int g = lane >> 2;
    const int q = (lane & 3) * 2;
#pragma unroll
    for (int i = 0; i < 2; i++) {
#pragma unroll
        for (int j = 0; j < 8; j++) {
            int row = bm + wm * 32 + i * 16 + g;
            int col = bn + wn * 64 + j * 8 + q;
            *(float2*)(C + (size_t)row * EMB + col) =
                make_float2(acc[i][j][0], acc[i][j][1]);
            *(float2*)(C + (size_t)(row + 8) * EMB + col) =
                make_float2(acc[i][j][2], acc[i][j][3]);
        }
    }
}

// ---------------- RoPE (in-place on q and k; q also scaled 1/sqrt(d)) -----
__global__ __launch_bounds__(256) void rope_kernel(
    float* __restrict__ q, float* __restrict__ k,
    const float* __restrict__ cosb, const float* __restrict__ sinb)
{
    int idx = blockIdx.x * blockDim.x + threadIdx.x;
    const int total = S_LEN * NHEAD * (HDIM / 2);
    if (idx >= total) return;
    int d2 = idx & 63;
    int h  = (idx >> 6) & (NHEAD - 1);
    int s  = idx >> 10;

    float c1 = cosb[s * HDIM + d2];
    float s1 = sinb[s * HDIM + d2];
    float c2 = cosb[s * HDIM + 64 + d2];
    float s2 = sinb[s * HDIM + 64 + d2];

    const float scale = 0.088388347648318447f;  // 1/sqrt(128)
    size_t base = (size_t)s * EMB + h * HDIM;

    float q1 = q[base + d2], q2 = q[base + 64 + d2];
    q[base + d2]      = (q1 * c1 - q2 * s1) * scale;
    q[base + 64 + d2] = (q2 * c2 + q1 * s2) * scale;

    float k1 = k[base + d2], k2 = k[base + 64 + d2];
    k[base + d2]      = k1 * c1 - k2 * s1;
    k[base + 64 + d2] = k2 * c2 + k1 * s2;
}

// ---------------- Flash attention (causal, fp32) ----------------
#define FL_SMEM_FLOATS (2 * 128 * 68 + 64 * 128 + 64 * 68 + 3 * 64)
#define FL_SMEM_BYTES  (FL_SMEM_FLOATS * 4)

__global__ __launch_bounds__(256) void flash_attn(
    const float* __restrict__ q, const float* __restrict__ k,
    const float* __restrict__ v, float* __restrict__ o)
{
    const int ib = blockIdx.x;    // q block: rows ib*64 ..
    const int h  = blockIdx.y;

    extern __shared__ __align__(16) float sm[];
    float* Qs = sm;                   // [128][68]  Qs[d][r]
    float* Ks = Qs + 128 * 68;        // [128][68]  Ks[d][r]
    float* Vs = Ks + 128 * 68;        // [64][128]  row-major
    float* Ss = Vs + 64 * 128;        // [64][68]
    float* ms = Ss + 64 * 68;
    float* ls = ms + 64;
    float* al = ls + 64;

    const int tid  = threadIdx.x;
    const int lane = tid & 31;
    const int w    = tid >> 5;
    const int tx   = tid & 15;
    const int ty   = tid >> 4;

    const int lr = (lane >> 2) + 8 * w;   // 0..63 (row within tile)
    const int lc = lane & 3;              // d-group base

    {
        const float* qrow = q + (size_t)(ib * 64 + lr) * EMB + h * HDIM;
#pragma unroll
        for (int it = 0; it < 8; it++) {
            int c4 = lc + 4 * it;
            float4 vq = *(const float4*)(qrow + c4 * 4);
            Qs[(c4 * 4 + 0) * 68 + lr] = vq.x;
            Qs[(c4 * 4 + 1) * 68 + lr] = vq.y;
            Qs[(c4 * 4 + 2) * 68 + lr] = vq.z;
            Qs[(c4 * 4 + 3) * 68 + lr] = vq.w;
        }
    }
    if (tid < 64) { ms[tid] = -1e30f; ls[tid] = 0.f; }

    float acc_o[4][8];
#pragma unroll
    for (int i = 0; i < 4; i++)
#pragma unroll
        for (int j = 0; j < 8; j++) acc_o[i][j] = 0.f;

    __syncthreads();

    for (int jb = 0; jb <= ib; jb++) {
        {
            const float* krow = k + (size_t)(jb * 64 + lr) * EMB + h * HDIM;
#pragma unroll
            for (int it = 0; it < 8; it++) {
                int c4 = lc + 4 * it;
                float4 vk = *(const float4*)(krow + c4 * 4);
                Ks[(c4 * 4 + 0) * 68 + lr] = vk.x;
                Ks[(c4 * 4 + 1) * 68 + lr] = vk.y;
                Ks[(c4 * 4 + 2) * 68 + lr] = vk.z;
                Ks[(c4 * 4 + 3) * 68 + lr] = vk.w;
            }
#pragma unroll
            for (int it = 0; it < 8; it++) {
                int i = tid + it * 256;
                int r = i >> 5, c4 = i & 31;
                *(float4*)(Vs + r * 128 + c4 * 4) =
                    *(const float4*)(v + (size_t)(jb * 64 + r) * EMB + h * HDIM + c4 * 4);
            }
        }
        __syncthreads();

        float s[4][4];
#pragma unroll
        for (int i = 0; i < 4; i++)
#pragma unroll
            for (int j = 0; j < 4; j++) s[i][j] = 0.f;

#pragma unroll 4
        for (int kk = 0; kk < 128; kk++) {
            float a[4], b[4];
            *(float4*)a = *(const float4*)(Qs + kk * 68 + ty * 4);
            *(float4*)b = *(const float4*)(Ks + kk * 68 + tx * 4);
#pragma unroll
            for (int i = 0; i < 4; i++)
#pragma unroll
                for (int j = 0; j < 4; j++)
                    s[i][j] = fmaf(a[i], b[j], s[i][j]);
        }

        const bool diag = (jb == ib);
#pragma unroll
        for (int i = 0; i < 4; i++) {
            int row = ty * 4 + i;
#pragma unroll
            for (int j = 0; j < 4; j++) {
                int col = tx * 4 + j;
                if (diag && col > row) s[i][j] = -1e30f;
            }
            float4 sv = make_float4(s[i][0], s[i][1], s[i][2], s[i][3]);
            *(float4*)(Ss + row * 68 + tx * 4) = sv;
        }
        __syncthreads();

        if (tid < 64) {
            float m_old = ms[tid];
            float mx = m_old;
#pragma unroll 8
            for (int j = 0; j < 64; j++) mx = fmaxf(mx, Ss[tid * 68 + j]);
            float alpha = __expf(m_old - mx);
            float sum = 0.f;
#pragma unroll 8
            for (int j = 0; j < 64; j++) {
                float p = __expf(Ss[tid * 68 + j] - mx);
                Ss[tid * 68 + j] = p;
                sum += p;
            }
            ms[tid] = mx;
            ls[tid] = ls[tid] * alpha + sum;
            al[tid] = alpha;
        }
        __syncthreads();

        float alpha_r[4];
#pragma unroll
        for (int i = 0; i < 4; i++) alpha_r[i] = al[ty * 4 + i];
#pragma unroll
        for (int i = 0; i < 4; i++)
#pragma unroll
            for (int j = 0; j < 8; j++) acc_o[i][j] *= alpha_r[i];

#pragma unroll 4
        for (int kk = 0; kk < 64; kk++) {
            float p[4], vv[8];
#pragma unroll
            for (int i = 0; i < 4; i++) p[i] = Ss[(ty * 4 + i) * 68 + kk];
            *(float4*)(vv)     = *(const float4*)(Vs + kk * 128 + tx * 4);
            *(float4*)(vv + 4) = *(const float4*)(Vs + kk * 128 + 64 + tx * 4);
#pragma unroll
            for (int i = 0; i < 4; i++)
#pragma unroll
                for (int j = 0; j < 8; j++)
                    acc_o[i][j] = fmaf(p[i], vv[j], acc_o[i][j]);
        }
        __syncthreads();
    }

#pragma unroll
    for (int i = 0; i < 4; i++) {
        int row = ty * 4 + i;
        float inv = 1.f / ls[row];
        size_t gbase = (size_t)(ib * 64 + row) * EMB + h * HDIM;
        float4 o0 = make_float4(acc_o[i][0] * inv, acc_o[i][1] * inv,
                                acc_o[i][2] * inv, acc_o[i][3] * inv);
        float4 o1 = make_float4(acc_o[i][4] * inv, acc_o[i][5] * inv,
                                acc_o[i][6] * inv, acc_o[i][7] * inv);
        *(float4*)(o + gbase + tx * 4)      = o0;
        *(float4*)(o + gbase + 64 + tx * 4) = o1;
    }
}

// ---------------- launch ----------------
extern "C" void kernel_launch(void* const* d_in, const int* in_sizes, int n_in,
                              void* d_out, int out_size)
{
    const float* x  = (const float*)d_in[0];
    const float* rc = (const float*)d_in[1];
    const float* rs = (const float*)d_in[2];
    const float* Wq = (const float*)d_in[3];
    const float* Wk = (const float*)d_in[4];
    const float* Wv = (const float*)d_in[5];
    const float* Wo = (const float*)d_in[6];
    float* out = (float*)d_out;

    float *q, *k, *v, *ao;
    cudaGetSymbolAddress((void**)&q,  g_q);
    cudaGetSymbolAddress((void**)&k,  g_k);
    cudaGetSymbolAddress((void**)&v,  g_v);
    cudaGetSymbolAddress((void**)&ao, g_ao);

    __nv_bfloat16 *xh, *xl, *qh, *ql, *kh, *kl, *vh, *vl, *oh, *ol, *aoh, *aol;
    cudaGetSymbolAddress((void**)&xh,  g_x_hi);
    cudaGetSymbolAddress((void**)&xl,  g_x_lo);
    cudaGetSymbolAddress((void**)&qh,  g_wq_hi);
    cudaGetSymbolAddress((void**)&ql,  g_wq_lo);
    cudaGetSymbolAddress((void**)&kh,  g_wk_hi);
    cudaGetSymbolAddress((void**)&kl,  g_wk_lo);
    cudaGetSymbolAddress((void**)&vh,  g_wv_hi);
    cudaGetSymbolAddress((void**)&vl,  g_wv_lo);
    cudaGetSymbolAddress((void**)&oh,  g_wo_hi);
    cudaGetSymbolAddress((void**)&ol,  g_wo_lo);
    cudaGetSymbolAddress((void**)&aoh, g_ao_hi);
    cudaGetSymbolAddress((void**)&aol, g_ao_lo);

    cudaFuncSetAttribute(flash_attn,
                         cudaFuncAttributeMaxDynamicSharedMemorySize, FL_SMEM_BYTES);
    cudaFuncSetAttribute(gemm_mma,
                         cudaFuncAttributeMaxDynamicSharedMemorySize, GM_SMEM);

    const int n = EMB * EMB;
    const int sb = (n / 4 + 255) / 256;

    split_kernel<<<sb, 256>>>(x,  xh, xl, n);
    split_kernel<<<sb, 256>>>(Wq, qh, ql, n);
    split_kernel<<<sb, 256>>>(Wk, kh, kl, n);
    split_kernel<<<sb, 256>>>(Wv, vh, vl, n);
    split_kernel<<<sb, 256>>>(Wo, oh, ol, n);

    dim3 gg(EMB / 256, S_LEN / 128);   // (8, 16) = 128 CTAs = one wave
    gemm_mma<<<gg, 512, GM_SMEM>>>(xh, xl, qh, ql, q);
    gemm_mma<<<gg, 512, GM_SMEM>>>(xh, xl, kh, kl, k);
    gemm_mma<<<gg, 512, GM_SMEM>>>(xh, xl, vh, vl, v);

    int rope_n = S_LEN * NHEAD * (HDIM / 2);
    rope_kernel<<<(rope_n + 255) / 256, 256>>>(q, k, rc, rs);

    flash_attn<<<dim3(S_LEN / 64, NHEAD), 256, FL_SMEM_BYTES>>>(q, k, v, ao);

    split_kernel<<<sb, 256>>>(ao, aoh, aol, n);
    gemm_mma<<<gg, 512, GM_SMEM>>>(aoh, aol, oh, ol, out);
}

// round 5
// speedup vs baseline: 2.1844x; 1.4437x over previous
#include <cuda_runtime.h>
#include <cuda_bf16.h>
#include <math.h>
#include <stdint.h>

#define S_LEN 2048
#define EMB   2048
#define NHEAD 16
#define HDIM  128

// ---------------- scratch (no cudaMalloc allowed) ----------------
__device__ float g_q [S_LEN * EMB];
__device__ float g_k [S_LEN * EMB];
__device__ float g_v [S_LEN * EMB];
__device__ float g_ao[S_LEN * EMB];

__device__ __nv_bfloat16 g_x_hi [S_LEN * EMB];
__device__ __nv_bfloat16 g_x_lo [S_LEN * EMB];
__device__ __nv_bfloat16 g_wq_hi[EMB * EMB];
__device__ __nv_bfloat16 g_wq_lo[EMB * EMB];
__device__ __nv_bfloat16 g_wk_hi[EMB * EMB];
__device__ __nv_bfloat16 g_wk_lo[EMB * EMB];
__device__ __nv_bfloat16 g_wv_hi[EMB * EMB];
__device__ __nv_bfloat16 g_wv_lo[EMB * EMB];
__device__ __nv_bfloat16 g_wo_hi[EMB * EMB];
__device__ __nv_bfloat16 g_wo_lo[EMB * EMB];
__device__ __nv_bfloat16 g_ao_hi[S_LEN * EMB];
__device__ __nv_bfloat16 g_ao_lo[S_LEN * EMB];

// attention operands (bf16 hi/lo)
__device__ __nv_bfloat16 g_qh [S_LEN * EMB];
__device__ __nv_bfloat16 g_ql [S_LEN * EMB];
__device__ __nv_bfloat16 g_kh [S_LEN * EMB];
__device__ __nv_bfloat16 g_kl [S_LEN * EMB];
__device__ __nv_bfloat16 g_vth[NHEAD * HDIM * S_LEN];   // [h][d][s]
__device__ __nv_bfloat16 g_vtl[NHEAD * HDIM * S_LEN];

// ================= helpers (baseline PTX only) ==============
__device__ __forceinline__ uint32_t s2u(const void* p) {
    uint32_t a;
    asm("{ .reg .u64 t; cvta.to.shared.u64 t, %1; cvt.u32.u64 %0, t; }"
        : "=r"(a) : "l"(p));
    return a;
}

__device__ __forceinline__ void cpa16(uint32_t dst, const void* src) {
    asm volatile("cp.async.cg.shared.global [%0], [%1], 16;" :: "r"(dst), "l"(src));
}
#define CPA_COMMIT() asm volatile("cp.async.commit_group;" ::: "memory")
#define CPA_WAIT1()  asm volatile("cp.async.wait_group 1;" ::: "memory")

__device__ __forceinline__ void ldsm4(uint32_t addr, uint32_t& r0, uint32_t& r1,
                                      uint32_t& r2, uint32_t& r3) {
    asm volatile("ldmatrix.sync.aligned.m8n8.x4.shared.b16 {%0,%1,%2,%3}, [%4];"
                 : "=r"(r0), "=r"(r1), "=r"(r2), "=r"(r3) : "r"(addr));
}

__device__ __forceinline__ void mma_bf16(float* d, const uint32_t* a,
                                         uint32_t b0, uint32_t b1) {
    asm volatile(
        "mma.sync.aligned.m16n8k16.row.col.f32.bf16.bf16.f32 "
        "{%0,%1,%2,%3}, {%4,%5,%6,%7}, {%8,%9}, {%0,%1,%2,%3};"
        : "+f"(d[0]), "+f"(d[1]), "+f"(d[2]), "+f"(d[3])
        : "r"(a[0]), "r"(a[1]), "r"(a[2]), "r"(a[3]), "r"(b0), "r"(b1));
}

__device__ __forceinline__ uint32_t b2u(__nv_bfloat162 v) {
    return *reinterpret_cast<uint32_t*>(&v);
}

// ================= split fp32 -> bf16 hi/lo ==============================
__global__ __launch_bounds__(256) void split_kernel(
    const float* __restrict__ src, __nv_bfloat16* __restrict__ hi,
    __nv_bfloat16* __restrict__ lo, int n)
{
    int i = (blockIdx.x * 256 + threadIdx.x) * 4;
    if (i >= n) return;
    float4 v = *(const float4*)(src + i);
    __nv_bfloat16 h0 = __float2bfloat16(v.x);
    __nv_bfloat16 h1 = __float2bfloat16(v.y);
    __nv_bfloat16 h2 = __float2bfloat16(v.z);
    __nv_bfloat16 h3 = __float2bfloat16(v.w);
    __nv_bfloat16 l0 = __float2bfloat16(v.x - __bfloat162float(h0));
    __nv_bfloat16 l1 = __float2bfloat16(v.y - __bfloat162float(h1));
    __nv_bfloat16 l2 = __float2bfloat16(v.z - __bfloat162float(h2));
    __nv_bfloat16 l3 = __float2bfloat16(v.w - __bfloat162float(h3));
    *(__nv_bfloat162*)(hi + i)     = __nv_bfloat162(h0, h1);
    *(__nv_bfloat162*)(hi + i + 2) = __nv_bfloat162(h2, h3);
    *(__nv_bfloat162*)(lo + i)     = __nv_bfloat162(l0, l1);
    *(__nv_bfloat162*)(lo + i + 2) = __nv_bfloat162(l2, l3);
}

// ================= mma.sync GEMM (unchanged from round 4) ================
#define ROWB     144
#define A_PL     18432
#define B_PL     36864
#define STAGE_B  110592
#define GM_SMEM  221184

__global__ __launch_bounds__(512, 1) void gemm_mma(
    const __nv_bfloat16* __restrict__ Ah, const __nv_bfloat16* __restrict__ Al,
    const __nv_bfloat16* __restrict__ Bh, const __nv_bfloat16* __restrict__ Bl,
    float* __restrict__ C)
{
    extern __shared__ char smraw[];
    const uint32_t sbase = s2u(smraw);

    const int tid  = threadIdx.x;
    const int lane = tid & 31;
    const int wid  = tid >> 5;
    const int wm   = wid & 3;
    const int wn   = wid >> 2;
    const int bm   = blockIdx.y * 128;
    const int bn   = blockIdx.x * 256;

    const int l   = lane & 7;
    const int mtx = lane >> 3;
    uint32_t offA[2], offB[4];
#pragma unroll
    for (int i = 0; i < 2; i++)
        offA[i] = (uint32_t)((wm * 32 + i * 16 + (mtx & 1) * 8 + l) * ROWB + (mtx >> 1) * 16);
#pragma unroll
    for (int j = 0; j < 4; j++)
        offB[j] = (uint32_t)((wn * 64 + j * 16 + (mtx >> 1) * 8 + l) * ROWB + (mtx & 1) * 16);

    float acc[2][8][4];
#pragma unroll
    for (int i = 0; i < 2; i++)
#pragma unroll
        for (int j = 0; j < 8; j++)
#pragma unroll
            for (int t = 0; t < 4; t++) acc[i][j][t] = 0.f;

    const int NST = EMB / 64;

    auto load_stage = [&](uint32_t bb, int k0) {
#pragma unroll
        for (int i = 0; i < 4; i++) {
            int e = tid + i * 512;
            int p = e >> 10;
            int r = (e >> 3) & 127;
            int c = e & 7;
            const __nv_bfloat16* s = (p ? Al : Ah) + (size_t)(bm + r) * EMB + k0 + c * 8;
            cpa16(bb + p * A_PL + r * ROWB + c * 16, s);
        }
#pragma unroll
        for (int i = 0; i < 8; i++) {
            int e = tid + i * 512;
            int p = e >> 11;
            int r = (e >> 3) & 255;
            int c = e & 7;
            const __nv_bfloat16* s = (p ? Bl : Bh) + (size_t)(bn + r) * EMB + k0 + c * 8;
            cpa16(bb + 2 * A_PL + p * B_PL + r * ROWB + c * 16, s);
        }
    };

    load_stage(sbase, 0);
    CPA_COMMIT();

    for (int s = 0; s < NST; s++) {
        if (s + 1 < NST)
            load_stage(sbase + ((s + 1) & 1) * STAGE_B, (s + 1) * 64);
        CPA_COMMIT();
        CPA_WAIT1();
        __syncthreads();

        const uint32_t bb = sbase + (s & 1) * STAGE_B;
#pragma unroll
        for (int pass = 0; pass < 3; pass++) {
            const uint32_t abase = bb + (pass == 2 ? A_PL : 0);
            const uint32_t bbase = bb + 2 * A_PL + (pass == 1 ? B_PL : 0);
#pragma unroll
            for (int ks = 0; ks < 4; ks++) {
                uint32_t a[2][4];
#pragma unroll
                for (int i = 0; i < 2; i++)
                    ldsm4(abase + offA[i] + ks * 32, a[i][0], a[i][1], a[i][2], a[i][3]);
                uint32_t b[4][4];
#pragma unroll
                for (int j = 0; j < 4; j++)
                    ldsm4(bbase + offB[j] + ks * 32, b[j][0], b[j][1], b[j][2], b[j][3]);
#pragma unroll
                for (int i = 0; i < 2; i++)
#pragma unroll
                    for (int j = 0; j < 4; j++) {
                        mma_bf16(acc[i][j * 2 + 0], a[i], b[j][0], b[j][1]);
                        mma_bf16(acc[i][j * 2 + 1], a[i], b[j][2], b[j][3]);
                    }
            }
        }
        __syncthreads();
    }

    const int g = lane >> 2;
    const int q = (lane & 3) * 2;
#pragma unroll
    for (int i = 0; i < 2; i++) {
#pragma unroll
        for (int j = 0; j < 8; j++) {
            int row = bm + wm * 32 + i * 16 + g;
            int col = bn + wn * 64 + j * 8 + q;
            *(float2*)(C + (size_t)row * EMB + col) =
                make_float2(acc[i][j][0], acc[i][j][1]);
            *(float2*)(C + (size_t)(row + 8) * EMB + col) =
                make_float2(acc[i][j][2], acc[i][j][3]);
        }
    }
}

// ---------------- RoPE + split q,k -> bf16 hi/lo --------------------------
__global__ __launch_bounds__(256) void rope_split(
    const float* __restrict__ q, const float* __restrict__ k,
    const float* __restrict__ cosb, const float* __restrict__ sinb,
    __nv_bfloat16* __restrict__ qh, __nv_bfloat16* __restrict__ ql,
    __nv_bfloat16* __restrict__ kh, __nv_bfloat16* __restrict__ kl)
{
    int idx = blockIdx.x * blockDim.x + threadIdx.x;
    const int total = S_LEN * NHEAD * (HDIM / 2);
    if (idx >= total) return;
    int d2 = idx & 63;
    int h  = (idx >> 6) & (NHEAD - 1);
    int s  = idx >> 10;

    float c1 = cosb[s * HDIM + d2];
    float s1 = sinb[s * HDIM + d2];
    float c2 = cosb[s * HDIM + 64 + d2];
    float s2 = sinb[s * HDIM + 64 + d2];

    const float scale = 0.088388347648318447f;  // 1/sqrt(128)
    size_t base = (size_t)s * EMB + h * HDIM;

    float q1 = q[base + d2], q2 = q[base + 64 + d2];
    float qa = (q1 * c1 - q2 * s1) * scale;
    float qb = (q2 * c2 + q1 * s2) * scale;
    float k1 = k[base + d2], k2 = k[base + 64 + d2];
    float ka = k1 * c1 - k2 * s1;
    float kb = k2 * c2 + k1 * s2;

    __nv_bfloat16 t;
    t = __float2bfloat16(qa); qh[base + d2] = t;      ql[base + d2]      = __float2bfloat16(qa - __bfloat162float(t));
    t = __float2bfloat16(qb); qh[base + 64 + d2] = t; ql[base + 64 + d2] = __float2bfloat16(qb - __bfloat162float(t));
    t = __float2bfloat16(ka); kh[base + d2] = t;      kl[base + d2]      = __float2bfloat16(ka - __bfloat162float(t));
    t = __float2bfloat16(kb); kh[base + 64 + d2] = t; kl[base + 64 + d2] = __float2bfloat16(kb - __bfloat162float(t));
}

// ---------------- V split + transpose: [s][h*128+d] -> [h][d][s] ----------
__global__ __launch_bounds__(256) void vsplit_t(
    const float* __restrict__ v,
    __nv_bfloat16* __restrict__ vth, __nv_bfloat16* __restrict__ vtl)
{
    __shared__ float t[64][65];
    const int sb = blockIdx.x * 64;
    const int db = blockIdx.y * 64;
    const int h  = blockIdx.z;
    const int tid = threadIdx.x;

#pragma unroll
    for (int it = 0; it < 16; it++) {
        int e = tid + it * 256;
        int r = e >> 6, c = e & 63;
        t[r][c] = v[(size_t)(sb + r) * EMB + h * HDIM + db + c];
    }
    __syncthreads();
#pragma unroll
    for (int it = 0; it < 16; it++) {
        int e = tid + it * 256;
        int r = e >> 6, c = e & 63;        // r: d index, c: s index
        float val = t[c][r];
        __nv_bfloat16 hi = __float2bfloat16(val);
        size_t o = (size_t)(h * HDIM + db + r) * S_LEN + sb + c;
        vth[o] = hi;
        vtl[o] = __float2bfloat16(val - __bfloat162float(hi));
    }
}

// ---------------- Flash attention (mma.sync, bf16x3) ----------------------
// CTA: 128 q-rows x 1 head; 8 warps (16 q-rows each); K-blocks of 64.
#define QB_ROW  272                    // 128 bf16 + 16B pad
#define KB_ROW  272
#define VB_ROW  144                    // 64 bf16 + 16B pad
#define SM_QPL  (128 * QB_ROW)         // 34816 per plane
#define SM_Q    (2 * SM_QPL)           // 69632
#define SM_KPL  (64 * KB_ROW)          // 17408
#define SM_VPL  (128 * VB_ROW)         // 18432
#define SM_KV   (2 * SM_KPL + 2 * SM_VPL)   // 71680 per buffer
#define FA_SMEM (SM_Q + 2 * SM_KV)     // 212992

__global__ __launch_bounds__(256, 1) void flash_mma(
    const __nv_bfloat16* __restrict__ qh, const __nv_bfloat16* __restrict__ ql,
    const __nv_bfloat16* __restrict__ kh, const __nv_bfloat16* __restrict__ kl,
    const __nv_bfloat16* __restrict__ vth, const __nv_bfloat16* __restrict__ vtl,
    float* __restrict__ o)
{
    extern __shared__ char smraw[];
    const uint32_t sQ = s2u(smraw);

    const int tid  = threadIdx.x;
    const int lane = tid & 31;
    const int w    = tid >> 5;
    const int g    = lane >> 2;
    const int qd   = lane & 3;
    const int l8   = lane & 7;
    const int mt   = lane >> 3;
    const int qbi  = blockIdx.x;       // q block (128 rows)
    const int h    = blockIdx.y;

    // ldmatrix offsets (mappings proven in gemm_mma)
    const uint32_t offAq = (uint32_t)((w * 16 + (mt & 1) * 8 + l8) * QB_ROW + (mt >> 1) * 16);
    uint32_t offBk[4], offBv[8];
#pragma unroll
    for (int j = 0; j < 4; j++)
        offBk[j] = (uint32_t)((j * 16 + (mt >> 1) * 8 + l8) * KB_ROW + (mt & 1) * 16);
#pragma unroll
    for (int j = 0; j < 8; j++)
        offBv[j] = (uint32_t)((j * 16 + (mt >> 1) * 8 + l8) * VB_ROW + (mt & 1) * 16);

    // ---- load Q (both planes) ----
#pragma unroll
    for (int i = 0; i < 16; i++) {
        int e = tid + i * 256;
        int p = e >> 11;
        int r = (e >> 4) & 127;
        int c = e & 15;
        const __nv_bfloat16* s = (p ? ql : qh) + (size_t)(qbi * 128 + r) * EMB + h * HDIM + c * 8;
        cpa16(sQ + p * SM_QPL + r * QB_ROW + c * 16, s);
    }

    auto load_kv = [&](int buf, int kb) {
        uint32_t kvb = sQ + SM_Q + buf * SM_KV;
#pragma unroll
        for (int i = 0; i < 8; i++) {           // K planes
            int e = tid + i * 256;
            int p = e >> 10;
            int r = (e >> 4) & 63;
            int c = e & 15;
            const __nv_bfloat16* s = (p ? kl : kh) + (size_t)(kb * 64 + r) * EMB + h * HDIM + c * 8;
            cpa16(kvb + p * SM_KPL + r * KB_ROW + c * 16, s);
        }
#pragma unroll
        for (int i = 0; i < 8; i++) {           // V planes (transposed)
            int e = tid + i * 256;
            int p = e >> 10;
            int r = (e >> 3) & 127;
            int c = e & 7;
            const __nv_bfloat16* s = (p ? vtl : vth) + (size_t)(h * HDIM + r) * S_LEN + kb * 64 + c * 8;
            cpa16(kvb + 2 * SM_KPL + p * SM_VPL + r * VB_ROW + c * 16, s);
        }
    };

    const int nkb = 2 * qbi + 2;
    load_kv(0, 0);
    CPA_COMMIT();

    float acco[16][4];
#pragma unroll
    for (int j = 0; j < 16; j++)
#pragma unroll
        for (int t = 0; t < 4; t++) acco[j][t] = 0.f;
    float m0 = -1e30f, m8 = -1e30f, l0 = 0.f, lsum8 = 0.f;

    const int row0 = qbi * 128 + w * 16 + g;
    const int row8 = row0 + 8;

    for (int kb = 0; kb < nkb; kb++) {
        if (kb + 1 < nkb) load_kv((kb + 1) & 1, kb + 1);
        CPA_COMMIT();
        CPA_WAIT1();
        __syncthreads();

        const uint32_t kvb = sQ + SM_Q + (kb & 1) * SM_KV;

        // ---- S = Q K^T (3 passes: qh*kh, qh*kl, ql*kh) ----
        float accs[8][4];
#pragma unroll
        for (int j = 0; j < 8; j++)
#pragma unroll
            for (int t = 0; t < 4; t++) accs[j][t] = 0.f;

        const uint32_t qoff[3] = {0u, 0u, (uint32_t)SM_QPL};
        const uint32_t koff[3] = {0u, (uint32_t)SM_KPL, 0u};
#pragma unroll
        for (int p = 0; p < 3; p++) {
#pragma unroll
            for (int ks = 0; ks < 8; ks++) {
                uint32_t a[4];
                ldsm4(sQ + qoff[p] + offAq + ks * 32, a[0], a[1], a[2], a[3]);
#pragma unroll
                for (int j = 0; j < 4; j++) {
                    uint32_t b0, b1, b2, b3;
                    ldsm4(kvb + koff[p] + offBk[j] + ks * 32, b0, b1, b2, b3);
                    mma_bf16(accs[j * 2 + 0], a, b0, b1);
                    mma_bf16(accs[j * 2 + 1], a, b2, b3);
                }
            }
        }

        // ---- causal mask (only needed on/after diagonal K-blocks) ----
        if (kb >= 2 * qbi) {
#pragma unroll
            for (int jt = 0; jt < 8; jt++) {
                int col = kb * 64 + jt * 8 + 2 * qd;
                if (col     > row0) accs[jt][0] = -1e30f;
                if (col + 1 > row0) accs[jt][1] = -1e30f;
                if (col     > row8) accs[jt][2] = -1e30f;
                if (col + 1 > row8) accs[jt][3] = -1e30f;
            }
        }

        // ---- online softmax ----
        float mx0 = -1e30f, mx8 = -1e30f;
#pragma unroll
        for (int jt = 0; jt < 8; jt++) {
            mx0 = fmaxf(mx0, fmaxf(accs[jt][0], accs[jt][1]));
            mx8 = fmaxf(mx8, fmaxf(accs[jt][2], accs[jt][3]));
        }
        mx0 = fmaxf(mx0, __shfl_xor_sync(0xffffffffu, mx0, 1));
        mx0 = fmaxf(mx0, __shfl_xor_sync(0xffffffffu, mx0, 2));
        mx8 = fmaxf(mx8, __shfl_xor_sync(0xffffffffu, mx8, 1));
        mx8 = fmaxf(mx8, __shfl_xor_sync(0xffffffffu, mx8, 2));

        float nm0 = fmaxf(m0, mx0), nm8 = fmaxf(m8, mx8);
        float al0 = __expf(m0 - nm0), al8 = __expf(m8 - nm8);
        m0 = nm0; m8 = nm8;

        float s0 = 0.f, s8 = 0.f;
#pragma unroll
        for (int jt = 0; jt < 8; jt++) {
            accs[jt][0] = __expf(accs[jt][0] - nm0);
            accs[jt][1] = __expf(accs[jt][1] - nm0);
            accs[jt][2] = __expf(accs[jt][2] - nm8);
            accs[jt][3] = __expf(accs[jt][3] - nm8);
            s0 += accs[jt][0] + accs[jt][1];
            s8 += accs[jt][2] + accs[jt][3];
        }
        s0 += __shfl_xor_sync(0xffffffffu, s0, 1);
        s0 += __shfl_xor_sync(0xffffffffu, s0, 2);
        s8 += __shfl_xor_sync(0xffffffffu, s8, 1);
        s8 += __shfl_xor_sync(0xffffffffu, s8, 2);
        l0 = l0 * al0 + s0;
        lsum8 = lsum8 * al8 + s8;

#pragma unroll
        for (int j = 0; j < 16; j++) {
            acco[j][0] *= al0; acco[j][1] *= al0;
            acco[j][2] *= al8; acco[j][3] *= al8;
        }

        // ---- split P into bf16 hi/lo fragments (registers only) ----
        uint32_t ph[8][2], pl[8][2];
#pragma unroll
        for (int jt = 0; jt < 8; jt++) {
            __nv_bfloat162 h2 = __floats2bfloat162_rn(accs[jt][0], accs[jt][1]);
            float2 hf = __bfloat1622float2(h2);
            ph[jt][0] = b2u(h2);
            pl[jt][0] = b2u(__floats2bfloat162_rn(accs[jt][0] - hf.x, accs[jt][1] - hf.y));
            h2 = __floats2bfloat162_rn(accs[jt][2], accs[jt][3]);
            hf = __bfloat1622float2(h2);
            ph[jt][1] = b2u(h2);
            pl[jt][1] = b2u(__floats2bfloat162_rn(accs[jt][2] - hf.x, accs[jt][3] - hf.y));
        }

        // ---- O += P V (3 passes: ph*vh, ph*vl, pl*vh) ----
        const uint32_t vbase = kvb + 2 * SM_KPL;
#pragma unroll
        for (int p = 0; p < 3; p++) {
            const uint32_t voff = (p == 1) ? (uint32_t)SM_VPL : 0u;
#pragma unroll
            for (int t = 0; t < 4; t++) {
                uint32_t a[4];
                if (p == 2) {
                    a[0] = pl[2 * t][0]; a[1] = pl[2 * t][1];
                    a[2] = pl[2 * t + 1][0]; a[3] = pl[2 * t + 1][1];
                } else {
                    a[0] = ph[2 * t][0]; a[1] = ph[2 * t][1];
                    a[2] = ph[2 * t + 1][0]; a[3] = ph[2 * t + 1][1];
                }
#pragma unroll
                for (int jn = 0; jn < 8; jn++) {
                    uint32_t b0, b1, b2, b3;
                    ldsm4(vbase + voff + offBv[jn] + t * 32, b0, b1, b2, b3);
                    mma_bf16(acco[jn * 2 + 0], a, b0, b1);
                    mma_bf16(acco[jn * 2 + 1], a, b2, b3);
                }
            }
        }
        __syncthreads();
    }

    // ---- epilogue ----
    float inv0 = 1.f / l0, inv8 = 1.f / lsum8;
#pragma unroll
    for (int jt = 0; jt < 16; jt++) {
        int col = h * HDIM + jt * 8 + 2 * qd;
        *(float2*)(o + (size_t)row0 * EMB + col) =
            make_float2(acco[jt][0] * inv0, acco[jt][1] * inv0);
        *(float2*)(o + (size_t)row8 * EMB + col) =
            make_float2(acco[jt][2] * inv8, acco[jt][3] * inv8);
    }
}

// ---------------- launch ----------------
extern "C" void kernel_launch(void* const* d_in, const int* in_sizes, int n_in,
                              void* d_out, int out_size)
{
    const float* x  = (const float*)d_in[0];
    const float* rc = (const float*)d_in[1];
    const float* rs = (const float*)d_in[2];
    const float* Wq = (const float*)d_in[3];
    const float* Wk = (const float*)d_in[4];
    const float* Wv = (const float*)d_in[5];
    const float* Wo = (const float*)d_in[6];
    float* out = (float*)d_out;

    float *q, *k, *v, *ao;
    cudaGetSymbolAddress((void**)&q,  g_q);
    cudaGetSymbolAddress((void**)&k,  g_k);
    cudaGetSymbolAddress((void**)&v,  g_v);
    cudaGetSymbolAddress((void**)&ao, g_ao);

    __nv_bfloat16 *xh, *xl, *wqh, *wql, *wkh, *wkl, *wvh, *wvl, *woh, *wol, *aoh, *aol;
    __nv_bfloat16 *qh, *ql, *kh, *kl, *vth, *vtl;
    cudaGetSymbolAddress((void**)&xh,  g_x_hi);
    cudaGetSymbolAddress((void**)&xl,  g_x_lo);
    cudaGetSymbolAddress((void**)&wqh, g_wq_hi);
    cudaGetSymbolAddress((void**)&wql, g_wq_lo);
    cudaGetSymbolAddress((void**)&wkh, g_wk_hi);
    cudaGetSymbolAddress((void**)&wkl, g_wk_lo);
    cudaGetSymbolAddress((void**)&wvh, g_wv_hi);
    cudaGetSymbolAddress((void**)&wvl, g_wv_lo);
    cudaGetSymbolAddress((void**)&woh, g_wo_hi);
    cudaGetSymbolAddress((void**)&wol, g_wo_lo);
    cudaGetSymbolAddress((void**)&aoh, g_ao_hi);
    cudaGetSymbolAddress((void**)&aol, g_ao_lo);
    cudaGetSymbolAddress((void**)&qh,  g_qh);
    cudaGetSymbolAddress((void**)&ql,  g_ql);
    cudaGetSymbolAddress((void**)&kh,  g_kh);
    cudaGetSymbolAddress((void**)&kl,  g_kl);
    cudaGetSymbolAddress((void**)&vth, g_vth);
    cudaGetSymbolAddress((void**)&vtl, g_vtl);

    cudaFuncSetAttribute(gemm_mma,
                         cudaFuncAttributeMaxDynamicSharedMemorySize, GM_SMEM);
    cudaFuncSetAttribute(flash_mma,
                         cudaFuncAttributeMaxDynamicSharedMemorySize, FA_SMEM);

    const int n = EMB * EMB;
    const int sb = (n / 4 + 255) / 256;

    split_kernel<<<sb, 256>>>(x,  xh, xl, n);
    split_kernel<<<sb, 256>>>(Wq, wqh, wql, n);
    split_kernel<<<sb, 256>>>(Wk, wkh, wkl, n);
    split_kernel<<<sb, 256>>>(Wv, wvh, wvl, n);
    split_kernel<<<sb, 256>>>(Wo, woh, wol, n);

    dim3 gg(EMB / 256, S_LEN / 128);   // 128 CTAs = one wave
    gemm_mma<<<gg, 512, GM_SMEM>>>(xh, xl, wqh, wql, q);
    gemm_mma<<<gg, 512, GM_SMEM>>>(xh, xl, wkh, wkl, k);
    gemm_mma<<<gg, 512, GM_SMEM>>>(xh, xl, wvh, wvl, v);

    int rope_n = S_LEN * NHEAD * (HDIM / 2);
    rope_split<<<(rope_n + 255) / 256, 256>>>(q, k, rc, rs, qh, ql, kh, kl);
    vsplit_t<<<dim3(S_LEN / 64, HDIM / 64, NHEAD), 256>>>(v, vth, vtl);

    flash_mma<<<dim3(S_LEN / 128, NHEAD), 256, FA_SMEM>>>(qh, ql, kh, kl, vth, vtl, ao);

    split_kernel<<<sb, 256>>>(ao, aoh, aol, n);
    gemm_mma<<<gg, 512, GM_SMEM>>>(aoh, aol, woh, wol, out);
}

// round 6
// speedup vs baseline: 4.9944x; 2.2864x over previous
#include <cuda_runtime.h>
#include <cuda_bf16.h>
#include <cuda_fp16.h>
#include <math.h>
#include <stdint.h>

#define S_LEN 2048
#define EMB   2048
#define NHEAD 16
#define HDIM  128

// ---------------- scratch (no cudaMalloc allowed) ----------------
__device__ float g_q [S_LEN * EMB];
__device__ float g_k [S_LEN * EMB];
__device__ float g_v [S_LEN * EMB];
__device__ float g_ao[S_LEN * EMB];

// packed fp16 GEMM operands (stage-contiguous, swizzled)
__device__ __align__(256) __half g_px [S_LEN * EMB];
__device__ __align__(256) __half g_pao[S_LEN * EMB];
__device__ __align__(256) __half g_pwq[EMB * EMB];
__device__ __align__(256) __half g_pwk[EMB * EMB];
__device__ __align__(256) __half g_pwv[EMB * EMB];
__device__ __align__(256) __half g_pwo[EMB * EMB];

// attention operands (bf16 hi/lo)
__device__ __nv_bfloat16 g_qh [S_LEN * EMB];
__device__ __nv_bfloat16 g_ql [S_LEN * EMB];
__device__ __nv_bfloat16 g_kh [S_LEN * EMB];
__device__ __nv_bfloat16 g_kl [S_LEN * EMB];
__device__ __nv_bfloat16 g_vth[NHEAD * HDIM * S_LEN];   // [h][d][s]
__device__ __nv_bfloat16 g_vtl[NHEAD * HDIM * S_LEN];

// ================= helpers (baseline PTX only) ==============
__device__ __forceinline__ uint32_t s2u(const void* p) {
    uint32_t a;
    asm("{ .reg .u64 t; cvta.to.shared.u64 t, %1; cvt.u32.u64 %0, t; }"
        : "=r"(a) : "l"(p));
    return a;
}

__device__ __forceinline__ void cpa16(uint32_t dst, const void* src) {
    asm volatile("cp.async.cg.shared.global [%0], [%1], 16;" :: "r"(dst), "l"(src));
}
#define CPA_COMMIT() asm volatile("cp.async.commit_group;" ::: "memory")
#define CPA_WAIT1()  asm volatile("cp.async.wait_group 1;" ::: "memory")

__device__ __forceinline__ void ldsm4(uint32_t addr, uint32_t& r0, uint32_t& r1,
                                      uint32_t& r2, uint32_t& r3) {
    asm volatile("ldmatrix.sync.aligned.m8n8.x4.shared.b16 {%0,%1,%2,%3}, [%4];"
                 : "=r"(r0), "=r"(r1), "=r"(r2), "=r"(r3) : "r"(addr));
}

__device__ __forceinline__ void mma_bf16(float* d, const uint32_t* a,
                                         uint32_t b0, uint32_t b1) {
    asm volatile(
        "mma.sync.aligned.m16n8k16.row.col.f32.bf16.bf16.f32 "
        "{%0,%1,%2,%3}, {%4,%5,%6,%7}, {%8,%9}, {%0,%1,%2,%3};"
        : "+f"(d[0]), "+f"(d[1]), "+f"(d[2]), "+f"(d[3])
        : "r"(a[0]), "r"(a[1]), "r"(a[2]), "r"(a[3]), "r"(b0), "r"(b1));
}

__device__ __forceinline__ void mma_f16(float* d, const uint32_t* a,
                                        uint32_t b0, uint32_t b1) {
    asm volatile(
        "mma.sync.aligned.m16n8k16.row.col.f32.f16.f16.f32 "
        "{%0,%1,%2,%3}, {%4,%5,%6,%7}, {%8,%9}, {%0,%1,%2,%3};"
        : "+f"(d[0]), "+f"(d[1]), "+f"(d[2]), "+f"(d[3])
        : "r"(a[0]), "r"(a[1]), "r"(a[2]), "r"(a[3]), "r"(b0), "r"(b1));
}

__device__ __forceinline__ uint32_t b2u(__nv_bfloat162 v) {
    return *reinterpret_cast<uint32_t*>(&v);
}

// ---- mbarrier / bulk-copy (sm_90 baseline PTX) ----
#define MBAR_INIT(mbar, cnt) \
    asm volatile("mbarrier.init.shared.b64 [%0], %1;" \
                 :: "r"((uint32_t)(mbar)), "r"((uint32_t)(cnt)) : "memory")
#define MBAR_EXPECT_TX(mbar, bytes) \
    asm volatile("mbarrier.arrive.expect_tx.shared.b64 _, [%0], %1;" \
                 :: "r"((uint32_t)(mbar)), "r"((uint32_t)(bytes)) : "memory")
#define MBAR_ARRIVE(mbar) \
    asm volatile("mbarrier.arrive.shared.b64 _, [%0];" \
                 :: "r"((uint32_t)(mbar)) : "memory")

__device__ __forceinline__ void mbar_wait(uint32_t mbar, uint32_t phase) {
    asm volatile(
        "{\n\t.reg .pred P1;\n\t"
        "WAIT_LOOP_%=:\n\t"
        "mbarrier.try_wait.parity.acquire.cta.shared::cta.b64 P1, [%0], %1, 0x989680;\n\t"
        "@P1 bra.uni WAIT_DONE_%=;\n\t"
        "bra.uni WAIT_LOOP_%=;\n\t"
        "WAIT_DONE_%=:\n\t}"
        :: "r"(mbar), "r"(phase) : "memory");
}

__device__ __forceinline__ void bulkcp(uint32_t dst, const void* src,
                                       uint32_t bytes, uint32_t mbar) {
    asm volatile(
        "cp.async.bulk.shared::cluster.global.mbarrier::complete_tx::bytes "
        "[%0], [%1], %2, [%3];"
        :: "r"(dst), "l"(src), "r"(bytes), "r"(mbar) : "memory");
}

// ================= repack fp32 -> fp16, stage-contiguous + XOR swizzle ====
// dst layout: [blk][ks][rin][chunk] where chunk = c ^ (rin & 7), 16B chunks.
// blkrows = 128 (A operands) or 256 (B operands). One block per source row.
__global__ __launch_bounds__(256) void conv_pack(
    const float* __restrict__ src, __half* __restrict__ dst, int blkrows)
{
    const int r   = blockIdx.x;            // global row
    const int t   = threadIdx.x;
    const int ks  = t >> 3;                // 0..31
    const int cs  = t & 7;                 // dst chunk (swizzled position)
    const int rin = r & (blkrows - 1);
    const int blk = r / blkrows;
    const int c   = cs ^ (rin & 7);        // source chunk

    const float* s = src + (size_t)r * EMB + ks * 64 + c * 8;
    float4 v0 = *(const float4*)(s);
    float4 v1 = *(const float4*)(s + 4);

    __half2 h0 = __floats2half2_rn(v0.x, v0.y);
    __half2 h1 = __floats2half2_rn(v0.z, v0.w);
    __half2 h2 = __floats2half2_rn(v1.x, v1.y);
    __half2 h3 = __floats2half2_rn(v1.z, v1.w);

    size_t chunk = ((size_t)(blk * 32 + ks) * blkrows + rin) * 8 + cs;
    uint4 out;
    out.x = *reinterpret_cast<uint32_t*>(&h0);
    out.y = *reinterpret_cast<uint32_t*>(&h1);
    out.z = *reinterpret_cast<uint32_t*>(&h2);
    out.w = *reinterpret_cast<uint32_t*>(&h3);
    *(reinterpret_cast<uint4*>(dst) + chunk) = out;
}

// ================= TMA-bulk fp16 GEMM: C[2048,2048] = A * B^T =============
// CTA tile 128x256, 8 warps (2x4), warp tile 64x64. K staged 64; 3-slot ring.
#define GB_A_BYTES 16384
#define GB_B_BYTES 32768
#define GB_STAGE   49152
#define GB_SMEM    (3 * GB_STAGE + 128)

__global__ __launch_bounds__(256, 1) void gemm_bulk(
    const __half* __restrict__ Ap, const __half* __restrict__ Bp,
    float* __restrict__ C)
{
    extern __shared__ char smraw[];
    const uint32_t sbase = s2u(smraw);
    const uint32_t mb    = sbase + 3 * GB_STAGE;   // full[i]=mb+i*16, empty=+8

    const int tid  = threadIdx.x;
    const int lane = tid & 31;
    const int wid  = tid >> 5;
    const int wm   = wid & 1;        // warp row -> rows wm*64
    const int wn   = wid >> 1;       // warp col (0..3) -> cols wn*64
    const int bm   = blockIdx.y * 128;
    const int bn   = blockIdx.x * 256;

    const int l8 = lane & 7;
    const int mt = lane >> 3;

    // per-lane fragment rows (proven mapping from gemm_mma)
    int rA[4], rB[4];
#pragma unroll
    for (int i = 0; i < 4; i++)
        rA[i] = wm * 64 + i * 16 + (mt & 1) * 8 + l8;
#pragma unroll
    for (int j = 0; j < 4; j++)
        rB[j] = wn * 64 + j * 16 + (mt >> 1) * 8 + l8;
    const int hcA = mt >> 1;    // chunk half-select for A
    const int hcB = mt & 1;     // for B

    float acc[4][8][4];
#pragma unroll
    for (int i = 0; i < 4; i++)
#pragma unroll
        for (int j = 0; j < 8; j++)
#pragma unroll
            for (int t = 0; t < 4; t++) acc[i][j][t] = 0.f;

    if (tid == 0) {
#pragma unroll
        for (int i = 0; i < 3; i++) {
            MBAR_INIT(mb + i * 16, 1);       // full
            MBAR_INIT(mb + i * 16 + 8, 8);   // empty (8 warps)
        }
    }
    __syncthreads();

    const __half* Asrc = Ap + (size_t)blockIdx.y * 32 * 128 * 64;
    const __half* Bsrc = Bp + (size_t)blockIdx.x * 32 * 256 * 64;

    if (tid == 0) {
#pragma unroll
        for (int i = 0; i < 3; i++) {
            MBAR_EXPECT_TX(mb + i * 16, GB_STAGE);
            bulkcp(sbase + i * GB_STAGE, Asrc + (size_t)i * 128 * 64,
                   GB_A_BYTES, mb + i * 16);
            bulkcp(sbase + i * GB_STAGE + GB_A_BYTES, Bsrc + (size_t)i * 256 * 64,
                   GB_B_BYTES, mb + i * 16);
        }
    }

    const int NST = EMB / 64;   // 32
    for (int s = 0; s < NST; s++) {
        const int sl = s - (s / 3) * 3;
        const uint32_t ph = (uint32_t)((s / 3) & 1);
        const uint32_t slot = sbase + sl * GB_STAGE;

        mbar_wait(mb + sl * 16, ph);

#pragma unroll
        for (int ks = 0; ks < 4; ks++) {
            uint32_t a[4][4];
#pragma unroll
            for (int i = 0; i < 4; i++) {
                uint32_t ch = (uint32_t)((2 * ks + hcA) ^ (rA[i] & 7));
                ldsm4(slot + rA[i] * 128 + ch * 16,
                      a[i][0], a[i][1], a[i][2], a[i][3]);
            }
            uint32_t b[4][4];
#pragma unroll
            for (int j = 0; j < 4; j++) {
                uint32_t ch = (uint32_t)((2 * ks + hcB) ^ (rB[j] & 7));
                ldsm4(slot + GB_A_BYTES + rB[j] * 128 + ch * 16,
                      b[j][0], b[j][1], b[j][2], b[j][3]);
            }
#pragma unroll
            for (int i = 0; i < 4; i++)
#pragma unroll
                for (int j = 0; j < 4; j++) {
                    mma_f16(acc[i][j * 2 + 0], a[i], b[j][0], b[j][1]);
                    mma_f16(acc[i][j * 2 + 1], a[i], b[j][2], b[j][3]);
                }
        }

        if (lane == 0) MBAR_ARRIVE(mb + sl * 16 + 8);   // warp done with slot

        if (tid == 0 && s + 3 < NST) {
            mbar_wait(mb + sl * 16 + 8, ph);            // all warps drained
            MBAR_EXPECT_TX(mb + sl * 16, GB_STAGE);
            bulkcp(slot, Asrc + (size_t)(s + 3) * 128 * 64,
                   GB_A_BYTES, mb + sl * 16);
            bulkcp(slot + GB_A_BYTES, Bsrc + (size_t)(s + 3) * 256 * 64,
                   GB_B_BYTES, mb + sl * 16);
        }
    }

    // epilogue
    const int g = lane >> 2;
    const int q = (lane & 3) * 2;
#pragma unroll
    for (int i = 0; i < 4; i++) {
#pragma unroll
        for (int j = 0; j < 8; j++) {
            int row = bm + wm * 64 + i * 16 + g;
            int col = bn + wn * 64 + j * 8 + q;
            *(float2*)(C + (size_t)row * EMB + col) =
                make_float2(acc[i][j][0], acc[i][j][1]);
            *(float2*)(C + (size_t)(row + 8) * EMB + col) =
                make_float2(acc[i][j][2], acc[i][j][3]);
        }
    }
}

// ---------------- RoPE + split q,k -> bf16 hi/lo --------------------------
__global__ __launch_bounds__(256) void rope_split(
    const float* __restrict__ q, const float* __restrict__ k,
    const float* __restrict__ cosb, const float* __restrict__ sinb,
    __nv_bfloat16* __restrict__ qh, __nv_bfloat16* __restrict__ ql,
    __nv_bfloat16* __restrict__ kh, __nv_bfloat16* __restrict__ kl)
{
    int idx = blockIdx.x * blockDim.x + threadIdx.x;
    const int total = S_LEN * NHEAD * (HDIM / 2);
    if (idx >= total) return;
    int d2 = idx & 63;
    int h  = (idx >> 6) & (NHEAD - 1);
    int s  = idx >> 10;

    float c1 = cosb[s * HDIM + d2];
    float s1 = sinb[s * HDIM + d2];
    float c2 = cosb[s * HDIM + 64 + d2];
    float s2 = sinb[s * HDIM + 64 + d2];

    const float scale = 0.088388347648318447f;  // 1/sqrt(128)
    size_t base = (size_t)s * EMB + h * HDIM;

    float q1 = q[base + d2], q2 = q[base + 64 + d2];
    float qa = (q1 * c1 - q2 * s1) * scale;
    float qb = (q2 * c2 + q1 * s2) * scale;
    float k1 = k[base + d2], k2 = k[base + 64 + d2];
    float ka = k1 * c1 - k2 * s1;
    float kb = k2 * c2 + k1 * s2;

    __nv_bfloat16 t;
    t = __float2bfloat16(qa); qh[base + d2] = t;      ql[base + d2]      = __float2bfloat16(qa - __bfloat162float(t));
    t = __float2bfloat16(qb); qh[base + 64 + d2] = t; ql[base + 64 + d2] = __float2bfloat16(qb - __bfloat162float(t));
    t = __float2bfloat16(ka); kh[base + d2] = t;      kl[base + d2]      = __float2bfloat16(ka - __bfloat162float(t));
    t = __float2bfloat16(kb); kh[base + 64 + d2] = t; kl[base + 64 + d2] = __float2bfloat16(kb - __bfloat162float(t));
}

// ---------------- V split + transpose: [s][h*128+d] -> [h][d][s] ----------
__global__ __launch_bounds__(256) void vsplit_t(
    const float* __restrict__ v,
    __nv_bfloat16* __restrict__ vth, __nv_bfloat16* __restrict__ vtl)
{
    __shared__ float t[64][65];
    const int sb = blockIdx.x * 64;
    const int db = blockIdx.y * 64;
    const int h  = blockIdx.z;
    const int tid = threadIdx.x;

#pragma unroll
    for (int it = 0; it < 16; it++) {
        int e = tid + it * 256;
        int r = e >> 6, c = e & 63;
        t[r][c] = v[(size_t)(sb + r) * EMB + h * HDIM + db + c];
    }
    __syncthreads();
#pragma unroll
    for (int it = 0; it < 16; it++) {
        int e = tid + it * 256;
        int r = e >> 6, c = e & 63;        // r: d index, c: s index
        float val = t[c][r];
        __nv_bfloat16 hi = __float2bfloat16(val);
        size_t o = (size_t)(h * HDIM + db + r) * S_LEN + sb + c;
        vth[o] = hi;
        vtl[o] = __float2bfloat16(val - __bfloat162float(hi));
    }
}

// ---------------- Flash attention (mma.sync, bf16x3) ----------------------
#define QB_ROW  272
#define KB_ROW  272
#define VB_ROW  144
#define SM_QPL  (128 * QB_ROW)
#define SM_Q    (2 * SM_QPL)
#define SM_KPL  (64 * KB_ROW)
#define SM_VPL  (128 * VB_ROW)
#define SM_KV   (2 * SM_KPL + 2 * SM_VPL)
#define FA_SMEM (SM_Q + 2 * SM_KV)

__global__ __launch_bounds__(256, 1) void flash_mma(
    const __nv_bfloat16* __restrict__ qh, const __nv_bfloat16* __restrict__ ql,
    const __nv_bfloat16* __restrict__ kh, const __nv_bfloat16* __restrict__ kl,
    const __nv_bfloat16* __restrict__ vth, const __nv_bfloat16* __restrict__ vtl,
    float* __restrict__ o)
{
    extern __shared__ char smraw[];
    const uint32_t sQ = s2u(smraw);

    const int tid  = threadIdx.x;
    const int lane = tid & 31;
    const int w    = tid >> 5;
    const int g    = lane >> 2;
    const int qd   = lane & 3;
    const int l8   = lane & 7;
    const int mt   = lane >> 3;
    const int qbi  = blockIdx.x;
    const int h    = blockIdx.y;

    const uint32_t offAq = (uint32_t)((w * 16 + (mt & 1) * 8 + l8) * QB_ROW + (mt >> 1) * 16);
    uint32_t offBk[4], offBv[8];
#pragma unroll
    for (int j = 0; j < 4; j++)
        offBk[j] = (uint32_t)((j * 16 + (mt >> 1) * 8 + l8) * KB_ROW + (mt & 1) * 16);
#pragma unroll
    for (int j = 0; j < 8; j++)
        offBv[j] = (uint32_t)((j * 16 + (mt >> 1) * 8 + l8) * VB_ROW + (mt & 1) * 16);

#pragma unroll
    for (int i = 0; i < 16; i++) {
        int e = tid + i * 256;
        int p = e >> 11;
        int r = (e >> 4) & 127;
        int c = e & 15;
        const __nv_bfloat16* s = (p ? ql : qh) + (size_t)(qbi * 128 + r) * EMB + h * HDIM + c * 8;
        cpa16(sQ + p * SM_QPL + r * QB_ROW + c * 16, s);
    }

    auto load_kv = [&](int buf, int kb) {
        uint32_t kvb = sQ + SM_Q + buf * SM_KV;
#pragma unroll
        for (int i = 0; i < 8; i++) {
            int e = tid + i * 256;
            int p = e >> 10;
            int r = (e >> 4) & 63;
            int c = e & 15;
            const __nv_bfloat16* s = (p ? kl : kh) + (size_t)(kb * 64 + r) * EMB + h * HDIM + c * 8;
            cpa16(kvb + p * SM_KPL + r * KB_ROW + c * 16, s);
        }
#pragma unroll
        for (int i = 0; i < 8; i++) {
            int e = tid + i * 256;
            int p = e >> 10;
            int r = (e >> 3) & 127;
            int c = e & 7;
            const __nv_bfloat16* s = (p ? vtl : vth) + (size_t)(h * HDIM + r) * S_LEN + kb * 64 + c * 8;
            cpa16(kvb + 2 * SM_KPL + p * SM_VPL + r * VB_ROW + c * 16, s);
        }
    };

    const int nkb = 2 * qbi + 2;
    load_kv(0, 0);
    CPA_COMMIT();

    float acco[16][4];
#pragma unroll
    for (int j = 0; j < 16; j++)
#pragma unroll
        for (int t = 0; t < 4; t++) acco[j][t] = 0.f;
    float m0 = -1e30f, m8 = -1e30f, l0 = 0.f, lsum8 = 0.f;

    const int row0 = qbi * 128 + w * 16 + g;
    const int row8 = row0 + 8;

    for (int kb = 0; kb < nkb; kb++) {
        if (kb + 1 < nkb) load_kv((kb + 1) & 1, kb + 1);
        CPA_COMMIT();
        CPA_WAIT1();
        __syncthreads();

        const uint32_t kvb = sQ + SM_Q + (kb & 1) * SM_KV;

        float accs[8][4];
#pragma unroll
        for (int j = 0; j < 8; j++)
#pragma unroll
            for (int t = 0; t < 4; t++) accs[j][t] = 0.f;

        const uint32_t qoff[3] = {0u, 0u, (uint32_t)SM_QPL};
        const uint32_t koff[3] = {0u, (uint32_t)SM_KPL, 0u};
#pragma unroll
        for (int p = 0; p < 3; p++) {
#pragma unroll
            for (int ks = 0; ks < 8; ks++) {
                uint32_t a[4];
                ldsm4(sQ + qoff[p] + offAq + ks * 32, a[0], a[1], a[2], a[3]);
#pragma unroll
                for (int j = 0; j < 4; j++) {
                    uint32_t b0, b1, b2, b3;
                    ldsm4(kvb + koff[p] + offBk[j] + ks * 32, b0, b1, b2, b3);
                    mma_bf16(accs[j * 2 + 0], a, b0, b1);
                    mma_bf16(accs[j * 2 + 1], a, b2, b3);
                }
            }
        }

        if (kb >= 2 * qbi) {
#pragma unroll
            for (int jt = 0; jt < 8; jt++) {
                int col = kb * 64 + jt * 8 + 2 * qd;
                if (col     > row0) accs[jt][0] = -1e30f;
                if (col + 1 > row0) accs[jt][1] = -1e30f;
                if (col     > row8) accs[jt][2] = -1e30f;
                if (col + 1 > row8) accs[jt][3] = -1e30f;
            }
        }

        float mx0 = -1e30f, mx8 = -1e30f;
#pragma unroll
        for (int jt = 0; jt < 8; jt++) {
            mx0 = fmaxf(mx0, fmaxf(accs[jt][0], accs[jt][1]));
            mx8 = fmaxf(mx8, fmaxf(accs[jt][2], accs[jt][3]));
        }
        mx0 = fmaxf(mx0, __shfl_xor_sync(0xffffffffu, mx0, 1));
        mx0 = fmaxf(mx0, __shfl_xor_sync(0xffffffffu, mx0, 2));
        mx8 = fmaxf(mx8, __shfl_xor_sync(0xffffffffu, mx8, 1));
        mx8 = fmaxf(mx8, __shfl_xor_sync(0xffffffffu, mx8, 2));

        float nm0 = fmaxf(m0, mx0), nm8 = fmaxf(m8, mx8);
        float al0 = __expf(m0 - nm0), al8 = __expf(m8 - nm8);
        m0 = nm0; m8 = nm8;

        float s0 = 0.f, s8 = 0.f;
#pragma unroll
        for (int jt = 0; jt < 8; jt++) {
            accs[jt][0] = __expf(accs[jt][0] - nm0);
            accs[jt][1] = __expf(accs[jt][1] - nm0);
            accs[jt][2] = __expf(accs[jt][2] - nm8);
            accs[jt][3] = __expf(accs[jt][3] - nm8);
            s0 += accs[jt][0] + accs[jt][1];
            s8 += accs[jt][2] + accs[jt][3];
        }
        s0 += __shfl_xor_sync(0xffffffffu, s0, 1);
        s0 += __shfl_xor_sync(0xffffffffu, s0, 2);
        s8 += __shfl_xor_sync(0xffffffffu, s8, 1);
        s8 += __shfl_xor_sync(0xffffffffu, s8, 2);
        l0 = l0 * al0 + s0;
        lsum8 = lsum8 * al8 + s8;

#pragma unroll
        for (int j = 0; j < 16; j++) {
            acco[j][0] *= al0; acco[j][1] *= al0;
            acco[j][2] *= al8; acco[j][3] *= al8;
        }

        uint32_t phh[8][2], pll[8][2];
#pragma unroll
        for (int jt = 0; jt < 8; jt++) {
            __nv_bfloat162 h2 = __floats2bfloat162_rn(accs[jt][0], accs[jt][1]);
            float2 hf = __bfloat1622float2(h2);
            phh[jt][0] = b2u(h2);
            pll[jt][0] = b2u(__floats2bfloat162_rn(accs[jt][0] - hf.x, accs[jt][1] - hf.y));
            h2 = __floats2bfloat162_rn(accs[jt][2], accs[jt][3]);
            hf = __bfloat1622float2(h2);
            phh[jt][1] = b2u(h2);
            pll[jt][1] = b2u(__floats2bfloat162_rn(accs[jt][2] - hf.x, accs[jt][3] - hf.y));
        }

        const uint32_t vbase = kvb + 2 * SM_KPL;
#pragma unroll
        for (int p = 0; p < 3; p++) {
            const uint32_t voff = (p == 1) ? (uint32_t)SM_VPL : 0u;
#pragma unroll
            for (int t = 0; t < 4; t++) {
                uint32_t a[4];
                if (p == 2) {
                    a[0] = pll[2 * t][0]; a[1] = pll[2 * t][1];
                    a[2] = pll[2 * t + 1][0]; a[3] = pll[2 * t + 1][1];
                } else {
                    a[0] = phh[2 * t][0]; a[1] = phh[2 * t][1];
                    a[2] = phh[2 * t + 1][0]; a[3] = phh[2 * t + 1][1];
                }
#pragma unroll
                for (int jn = 0; jn < 8; jn++) {
                    uint32_t b0, b1, b2, b3;
                    ldsm4(vbase + voff + offBv[jn] + t * 32, b0, b1, b2, b3);
                    mma_bf16(acco[jn * 2 + 0], a, b0, b1);
                    mma_bf16(acco[jn * 2 + 1], a, b2, b3);
                }
            }
        }
        __syncthreads();
    }

    float inv0 = 1.f / l0, inv8 = 1.f / lsum8;
#pragma unroll
    for (int jt = 0; jt < 16; jt++) {
        int col = h * HDIM + jt * 8 + 2 * qd;
        *(float2*)(o + (size_t)row0 * EMB + col) =
            make_float2(acco[jt][0] * inv0, acco[jt][1] * inv0);
        *(float2*)(o + (size_t)row8 * EMB + col) =
            make_float2(acco[jt][2] * inv8, acco[jt][3] * inv8);
    }
}

// ---------------- launch ----------------
extern "C" void kernel_launch(void* const* d_in, const int* in_sizes, int n_in,
                              void* d_out, int out_size)
{
    const float* x  = (const float*)d_in[0];
    const float* rc = (const float*)d_in[1];
    const float* rs = (const float*)d_in[2];
    const float* Wq = (const float*)d_in[3];
    const float* Wk = (const float*)d_in[4];
    const float* Wv = (const float*)d_in[5];
    const float* Wo = (const float*)d_in[6];
    float* out = (float*)d_out;

    float *q, *k, *v, *ao;
    cudaGetSymbolAddress((void**)&q,  g_q);
    cudaGetSymbolAddress((void**)&k,  g_k);
    cudaGetSymbolAddress((void**)&v,  g_v);
    cudaGetSymbolAddress((void**)&ao, g_ao);

    __half *px, *pao, *pwq, *pwk, *pwv, *pwo;
    cudaGetSymbolAddress((void**)&px,  g_px);
    cudaGetSymbolAddress((void**)&pao, g_pao);
    cudaGetSymbolAddress((void**)&pwq, g_pwq);
    cudaGetSymbolAddress((void**)&pwk, g_pwk);
    cudaGetSymbolAddress((void**)&pwv, g_pwv);
    cudaGetSymbolAddress((void**)&pwo, g_pwo);

    __nv_bfloat16 *qh, *ql, *kh, *kl, *vth, *vtl;
    cudaGetSymbolAddress((void**)&qh,  g_qh);
    cudaGetSymbolAddress((void**)&ql,  g_ql);
    cudaGetSymbolAddress((void**)&kh,  g_kh);
    cudaGetSymbolAddress((void**)&kl,  g_kl);
    cudaGetSymbolAddress((void**)&vth, g_vth);
    cudaGetSymbolAddress((void**)&vtl, g_vtl);

    cudaFuncSetAttribute(gemm_bulk,
                         cudaFuncAttributeMaxDynamicSharedMemorySize, GB_SMEM);
    cudaFuncSetAttribute(flash_mma,
                         cudaFuncAttributeMaxDynamicSharedMemorySize, FA_SMEM);

    // repack (A-type: blkrows=128; B-type: blkrows=256)
    conv_pack<<<S_LEN, 256>>>(x,  px,  128);
    conv_pack<<<EMB,   256>>>(Wq, pwq, 256);
    conv_pack<<<EMB,   256>>>(Wk, pwk, 256);
    conv_pack<<<EMB,   256>>>(Wv, pwv, 256);
    conv_pack<<<EMB,   256>>>(Wo, pwo, 256);

    dim3 gg(EMB / 256, S_LEN / 128);   // (8, 16) = 128 CTAs
    gemm_bulk<<<gg, 256, GB_SMEM>>>(px, pwq, q);
    gemm_bulk<<<gg, 256, GB_SMEM>>>(px, pwk, k);
    gemm_bulk<<<gg, 256, GB_SMEM>>>(px, pwv, v);

    int rope_n = S_LEN * NHEAD * (HDIM / 2);
    rope_split<<<(rope_n + 255) / 256, 256>>>(q, k, rc, rs, qh, ql, kh, kl);
    vsplit_t<<<dim3(S_LEN / 64, HDIM / 64, NHEAD), 256>>>(v, vth, vtl);

    flash_mma<<<dim3(S_LEN / 128, NHEAD), 256, FA_SMEM>>>(qh, ql, kh, kl, vth, vtl, ao);

    conv_pack<<<S_LEN, 256>>>(ao, pao, 128);
    gemm_bulk<<<gg, 256, GB_SMEM>>>(pao, pwo, out);
}

// round 7
// speedup vs baseline: 5.2565x; 1.0525x over previous
#include <cuda_runtime.h>
#include <cuda_bf16.h>
#include <cuda_fp16.h>
#include <math.h>
#include <stdint.h>

#define S_LEN 2048
#define EMB   2048
#define NHEAD 16
#define HDIM  128

// ---------------- scratch (no cudaMalloc allowed) ----------------
__device__ float g_q [S_LEN * EMB];
__device__ float g_k [S_LEN * EMB];
__device__ float g_v [S_LEN * EMB];
__device__ float g_ao[S_LEN * EMB];

// packed fp16 GEMM operands (stage-contiguous, swizzled)
__device__ __align__(256) __half g_px [S_LEN * EMB];
__device__ __align__(256) __half g_pao[S_LEN * EMB];
__device__ __align__(256) __half g_pwq[EMB * EMB];
__device__ __align__(256) __half g_pwk[EMB * EMB];
__device__ __align__(256) __half g_pwv[EMB * EMB];
__device__ __align__(256) __half g_pwo[EMB * EMB];

// attention operands (bf16 hi/lo)
__device__ __nv_bfloat16 g_qh [S_LEN * EMB];
__device__ __nv_bfloat16 g_ql [S_LEN * EMB];
__device__ __nv_bfloat16 g_kh [S_LEN * EMB];
__device__ __nv_bfloat16 g_kl [S_LEN * EMB];
__device__ __nv_bfloat16 g_vth[NHEAD * HDIM * S_LEN];   // [h][d][s]
__device__ __nv_bfloat16 g_vtl[NHEAD * HDIM * S_LEN];

// ================= helpers (baseline PTX only) ==============
__device__ __forceinline__ uint32_t s2u(const void* p) {
    uint32_t a;
    asm("{ .reg .u64 t; cvta.to.shared.u64 t, %1; cvt.u32.u64 %0, t; }"
        : "=r"(a) : "l"(p));
    return a;
}

__device__ __forceinline__ void cpa16(uint32_t dst, const void* src) {
    asm volatile("cp.async.cg.shared.global [%0], [%1], 16;" :: "r"(dst), "l"(src));
}
#define CPA_COMMIT() asm volatile("cp.async.commit_group;" ::: "memory")
#define CPA_WAIT1()  asm volatile("cp.async.wait_group 1;" ::: "memory")

__device__ __forceinline__ void ldsm4(uint32_t addr, uint32_t& r0, uint32_t& r1,
                                      uint32_t& r2, uint32_t& r3) {
    asm volatile("ldmatrix.sync.aligned.m8n8.x4.shared.b16 {%0,%1,%2,%3}, [%4];"
                 : "=r"(r0), "=r"(r1), "=r"(r2), "=r"(r3) : "r"(addr));
}

__device__ __forceinline__ void mma_bf16(float* d, const uint32_t* a,
                                         uint32_t b0, uint32_t b1) {
    asm volatile(
        "mma.sync.aligned.m16n8k16.row.col.f32.bf16.bf16.f32 "
        "{%0,%1,%2,%3}, {%4,%5,%6,%7}, {%8,%9}, {%0,%1,%2,%3};"
        : "+f"(d[0]), "+f"(d[1]), "+f"(d[2]), "+f"(d[3])
        : "r"(a[0]), "r"(a[1]), "r"(a[2]), "r"(a[3]), "r"(b0), "r"(b1));
}

__device__ __forceinline__ void mma_f16(float* d, const uint32_t* a,
                                        uint32_t b0, uint32_t b1) {
    asm volatile(
        "mma.sync.aligned.m16n8k16.row.col.f32.f16.f16.f32 "
        "{%0,%1,%2,%3}, {%4,%5,%6,%7}, {%8,%9}, {%0,%1,%2,%3};"
        : "+f"(d[0]), "+f"(d[1]), "+f"(d[2]), "+f"(d[3])
        : "r"(a[0]), "r"(a[1]), "r"(a[2]), "r"(a[3]), "r"(b0), "r"(b1));
}

__device__ __forceinline__ uint32_t b2u(__nv_bfloat162 v) {
    return *reinterpret_cast<uint32_t*>(&v);
}

// ---- mbarrier / bulk-copy (sm_90 baseline PTX) ----
#define MBAR_INIT(mbar, cnt) \
    asm volatile("mbarrier.init.shared.b64 [%0], %1;" \
                 :: "r"((uint32_t)(mbar)), "r"((uint32_t)(cnt)) : "memory")
#define MBAR_EXPECT_TX(mbar, bytes) \
    asm volatile("mbarrier.arrive.expect_tx.shared.b64 _, [%0], %1;" \
                 :: "r"((uint32_t)(mbar)), "r"((uint32_t)(bytes)) : "memory")
#define MBAR_ARRIVE(mbar) \
    asm volatile("mbarrier.arrive.shared.b64 _, [%0];" \
                 :: "r"((uint32_t)(mbar)) : "memory")

__device__ __forceinline__ void mbar_wait(uint32_t mbar, uint32_t phase) {
    asm volatile(
        "{\n\t.reg .pred P1;\n\t"
        "WAIT_LOOP_%=:\n\t"
        "mbarrier.try_wait.parity.acquire.cta.shared::cta.b64 P1, [%0], %1, 0x989680;\n\t"
        "@P1 bra.uni WAIT_DONE_%=;\n\t"
        "bra.uni WAIT_LOOP_%=;\n\t"
        "WAIT_DONE_%=:\n\t}"
        :: "r"(mbar), "r"(phase) : "memory");
}

__device__ __forceinline__ void bulkcp(uint32_t dst, const void* src,
                                       uint32_t bytes, uint32_t mbar) {
    asm volatile(
        "cp.async.bulk.shared::cluster.global.mbarrier::complete_tx::bytes "
        "[%0], [%1], %2, [%3];"
        :: "r"(dst), "l"(src), "r"(bytes), "r"(mbar) : "memory");
}

// ================= repack fp32 -> fp16, stage-contiguous + XOR swizzle ====
__device__ __forceinline__ void pack_row(
    const float* __restrict__ src, __half* __restrict__ dst,
    int r, int t, int blkrows)
{
    const int ks  = t >> 3;
    const int cs  = t & 7;
    const int rin = r & (blkrows - 1);
    const int blk = r / blkrows;
    const int c   = cs ^ (rin & 7);

    const float* s = src + (size_t)r * EMB + ks * 64 + c * 8;
    float4 v0 = *(const float4*)(s);
    float4 v1 = *(const float4*)(s + 4);

    __half2 h0 = __floats2half2_rn(v0.x, v0.y);
    __half2 h1 = __floats2half2_rn(v0.z, v0.w);
    __half2 h2 = __floats2half2_rn(v1.x, v1.y);
    __half2 h3 = __floats2half2_rn(v1.z, v1.w);

    size_t chunk = ((size_t)(blk * 32 + ks) * blkrows + rin) * 8 + cs;
    uint4 out;
    out.x = *reinterpret_cast<uint32_t*>(&h0);
    out.y = *reinterpret_cast<uint32_t*>(&h1);
    out.z = *reinterpret_cast<uint32_t*>(&h2);
    out.w = *reinterpret_cast<uint32_t*>(&h3);
    *(reinterpret_cast<uint4*>(dst) + chunk) = out;
}

__global__ __launch_bounds__(256) void conv_pack(
    const float* __restrict__ src, __half* __restrict__ dst, int blkrows)
{
    pack_row(src, dst, blockIdx.x, threadIdx.x, blkrows);
}

// pack all 4 weights in one launch (blockIdx.y selects the weight)
__global__ __launch_bounds__(256) void conv_pack_w4(
    const float* __restrict__ w0, const float* __restrict__ w1,
    const float* __restrict__ w2, const float* __restrict__ w3,
    __half* __restrict__ d0, __half* __restrict__ d1,
    __half* __restrict__ d2, __half* __restrict__ d3)
{
    const float* s;
    __half* d;
    switch (blockIdx.y) {
        case 0: s = w0; d = d0; break;
        case 1: s = w1; d = d1; break;
        case 2: s = w2; d = d2; break;
        default: s = w3; d = d3; break;
    }
    pack_row(s, d, blockIdx.x, threadIdx.x, 256);
}

// ================= TMA-bulk fp16 GEMM: C[2048,2048] = A * B^T =============
#define GB_A_BYTES 16384
#define GB_B_BYTES 32768
#define GB_STAGE   49152
#define GB_SMEM    (3 * GB_STAGE + 128)

__device__ __forceinline__ void gemm_bulk_body(
    const __half* __restrict__ Ap, const __half* __restrict__ Bp,
    float* __restrict__ C, int bx, int by)
{
    extern __shared__ char smraw[];
    const uint32_t sbase = s2u(smraw);
    const uint32_t mb    = sbase + 3 * GB_STAGE;

    const int tid  = threadIdx.x;
    const int lane = tid & 31;
    const int wid  = tid >> 5;
    const int wm   = wid & 1;
    const int wn   = wid >> 1;
    const int bm   = by * 128;
    const int bn   = bx * 256;

    const int l8 = lane & 7;
    const int mt = lane >> 3;

    int rA[4], rB[4];
#pragma unroll
    for (int i = 0; i < 4; i++)
        rA[i] = wm * 64 + i * 16 + (mt & 1) * 8 + l8;
#pragma unroll
    for (int j = 0; j < 4; j++)
        rB[j] = wn * 64 + j * 16 + (mt >> 1) * 8 + l8;
    const int hcA = mt >> 1;
    const int hcB = mt & 1;

    float acc[4][8][4];
#pragma unroll
    for (int i = 0; i < 4; i++)
#pragma unroll
        for (int j = 0; j < 8; j++)
#pragma unroll
            for (int t = 0; t < 4; t++) acc[i][j][t] = 0.f;

    if (tid == 0) {
#pragma unroll
        for (int i = 0; i < 3; i++) {
            MBAR_INIT(mb + i * 16, 1);
            MBAR_INIT(mb + i * 16 + 8, 8);
        }
    }
    __syncthreads();

    const __half* Asrc = Ap + (size_t)by * 32 * 128 * 64;
    const __half* Bsrc = Bp + (size_t)bx * 32 * 256 * 64;

    if (tid == 0) {
#pragma unroll
        for (int i = 0; i < 3; i++) {
            MBAR_EXPECT_TX(mb + i * 16, GB_STAGE);
            bulkcp(sbase + i * GB_STAGE, Asrc + (size_t)i * 128 * 64,
                   GB_A_BYTES, mb + i * 16);
            bulkcp(sbase + i * GB_STAGE + GB_A_BYTES, Bsrc + (size_t)i * 256 * 64,
                   GB_B_BYTES, mb + i * 16);
        }
    }

    const int NST = EMB / 64;
    for (int s = 0; s < NST; s++) {
        const int sl = s - (s / 3) * 3;
        const uint32_t ph = (uint32_t)((s / 3) & 1);
        const uint32_t slot = sbase + sl * GB_STAGE;

        mbar_wait(mb + sl * 16, ph);

#pragma unroll
        for (int ks = 0; ks < 4; ks++) {
            uint32_t a[4][4];
#pragma unroll
            for (int i = 0; i < 4; i++) {
                uint32_t ch = (uint32_t)((2 * ks + hcA) ^ (rA[i] & 7));
                ldsm4(slot + rA[i] * 128 + ch * 16,
                      a[i][0], a[i][1], a[i][2], a[i][3]);
            }
            uint32_t b[4][4];
#pragma unroll
            for (int j = 0; j < 4; j++) {
                uint32_t ch = (uint32_t)((2 * ks + hcB) ^ (rB[j] & 7));
                ldsm4(slot + GB_A_BYTES + rB[j] * 128 + ch * 16,
                      b[j][0], b[j][1], b[j][2], b[j][3]);
            }
#pragma unroll
            for (int i = 0; i < 4; i++)
#pragma unroll
                for (int j = 0; j < 4; j++) {
                    mma_f16(acc[i][j * 2 + 0], a[i], b[j][0], b[j][1]);
                    mma_f16(acc[i][j * 2 + 1], a[i], b[j][2], b[j][3]);
                }
        }

        if (lane == 0) MBAR_ARRIVE(mb + sl * 16 + 8);

        if (tid == 0 && s + 3 < NST) {
            mbar_wait(mb + sl * 16 + 8, ph);
            MBAR_EXPECT_TX(mb + sl * 16, GB_STAGE);
            bulkcp(slot, Asrc + (size_t)(s + 3) * 128 * 64,
                   GB_A_BYTES, mb + sl * 16);
            bulkcp(slot + GB_A_BYTES, Bsrc + (size_t)(s + 3) * 256 * 64,
                   GB_B_BYTES, mb + sl * 16);
        }
    }

    const int g = lane >> 2;
    const int q = (lane & 3) * 2;
#pragma unroll
    for (int i = 0; i < 4; i++) {
#pragma unroll
        for (int j = 0; j < 8; j++) {
            int row = bm + wm * 64 + i * 16 + g;
            int col = bn + wn * 64 + j * 8 + q;
            *(float2*)(C + (size_t)row * EMB + col) =
                make_float2(acc[i][j][0], acc[i][j][1]);
            *(float2*)(C + (size_t)(row + 8) * EMB + col) =
                make_float2(acc[i][j][2], acc[i][j][3]);
        }
    }
}

__global__ __launch_bounds__(256, 1) void gemm_bulk(
    const __half* __restrict__ Ap, const __half* __restrict__ Bp,
    float* __restrict__ C)
{
    gemm_bulk_body(Ap, Bp, C, blockIdx.x, blockIdx.y);
}

// fused QKV: blockIdx.z selects weight/output
__global__ __launch_bounds__(256, 1) void gemm_bulk_qkv(
    const __half* __restrict__ Ap,
    const __half* __restrict__ Bq, const __half* __restrict__ Bk,
    const __half* __restrict__ Bv,
    float* __restrict__ Cq, float* __restrict__ Ck, float* __restrict__ Cv)
{
    const __half* Bp;
    float* C;
    switch (blockIdx.z) {
        case 0:  Bp = Bq; C = Cq; break;
        case 1:  Bp = Bk; C = Ck; break;
        default: Bp = Bv; C = Cv; break;
    }
    gemm_bulk_body(Ap, Bp, C, blockIdx.x, blockIdx.y);
}

// ---------------- RoPE + split q,k -> bf16 hi/lo --------------------------
__global__ __launch_bounds__(256) void rope_split(
    const float* __restrict__ q, const float* __restrict__ k,
    const float* __restrict__ cosb, const float* __restrict__ sinb,
    __nv_bfloat16* __restrict__ qh, __nv_bfloat16* __restrict__ ql,
    __nv_bfloat16* __restrict__ kh, __nv_bfloat16* __restrict__ kl)
{
    int idx = blockIdx.x * blockDim.x + threadIdx.x;
    const int total = S_LEN * NHEAD * (HDIM / 2);
    if (idx >= total) return;
    int d2 = idx & 63;
    int h  = (idx >> 6) & (NHEAD - 1);
    int s  = idx >> 10;

    float c1 = cosb[s * HDIM + d2];
    float s1 = sinb[s * HDIM + d2];
    float c2 = cosb[s * HDIM + 64 + d2];
    float s2 = sinb[s * HDIM + 64 + d2];

    const float scale = 0.088388347648318447f;  // 1/sqrt(128)
    size_t base = (size_t)s * EMB + h * HDIM;

    float q1 = q[base + d2], q2 = q[base + 64 + d2];
    float qa = (q1 * c1 - q2 * s1) * scale;
    float qb = (q2 * c2 + q1 * s2) * scale;
    float k1 = k[base + d2], k2 = k[base + 64 + d2];
    float ka = k1 * c1 - k2 * s1;
    float kb = k2 * c2 + k1 * s2;

    __nv_bfloat16 t;
    t = __float2bfloat16(qa); qh[base + d2] = t;      ql[base + d2]      = __float2bfloat16(qa - __bfloat162float(t));
    t = __float2bfloat16(qb); qh[base + 64 + d2] = t; ql[base + 64 + d2] = __float2bfloat16(qb - __bfloat162float(t));
    t = __float2bfloat16(ka); kh[base + d2] = t;      kl[base + d2]      = __float2bfloat16(ka - __bfloat162float(t));
    t = __float2bfloat16(kb); kh[base + 64 + d2] = t; kl[base + 64 + d2] = __float2bfloat16(kb - __bfloat162float(t));
}

// ---------------- V split + transpose: [s][h*128+d] -> [h][d][s] ----------
__global__ __launch_bounds__(256) void vsplit_t(
    const float* __restrict__ v,
    __nv_bfloat16* __restrict__ vth, __nv_bfloat16* __restrict__ vtl)
{
    __shared__ float t[64][65];
    const int sb = blockIdx.x * 64;
    const int db = blockIdx.y * 64;
    const int h  = blockIdx.z;
    const int tid = threadIdx.x;

#pragma unroll
    for (int it = 0; it < 16; it++) {
        int e = tid + it * 256;
        int r = e >> 6, c = e & 63;
        t[r][c] = v[(size_t)(sb + r) * EMB + h * HDIM + db + c];
    }
    __syncthreads();
#pragma unroll
    for (int it = 0; it < 16; it++) {
        int e = tid + it * 256;
        int r = e >> 6, c = e & 63;
        float val = t[c][r];
        __nv_bfloat16 hi = __float2bfloat16(val);
        size_t o = (size_t)(h * HDIM + db + r) * S_LEN + sb + c;
        vth[o] = hi;
        vtl[o] = __float2bfloat16(val - __bfloat162float(hi));
    }
}

// ---------------- Flash attention (mma.sync, bf16x3) ----------------------
#define QB_ROW  272
#define KB_ROW  272
#define VB_ROW  144
#define SM_QPL  (128 * QB_ROW)
#define SM_Q    (2 * SM_QPL)
#define SM_KPL  (64 * KB_ROW)
#define SM_VPL  (128 * VB_ROW)
#define SM_KV   (2 * SM_KPL + 2 * SM_VPL)
#define FA_SMEM (SM_Q + 2 * SM_KV)

__global__ __launch_bounds__(256, 1) void flash_mma(
    const __nv_bfloat16* __restrict__ qh, const __nv_bfloat16* __restrict__ ql,
    const __nv_bfloat16* __restrict__ kh, const __nv_bfloat16* __restrict__ kl,
    const __nv_bfloat16* __restrict__ vth, const __nv_bfloat16* __restrict__ vtl,
    float* __restrict__ o)
{
    extern __shared__ char smraw[];
    const uint32_t sQ = s2u(smraw);

    const int tid  = threadIdx.x;
    const int lane = tid & 31;
    const int w    = tid >> 5;
    const int g    = lane >> 2;
    const int qd   = lane & 3;
    const int l8   = lane & 7;
    const int mt   = lane >> 3;
    const int qbi  = gridDim.x - 1 - blockIdx.x;   // heaviest CTAs first
    const int h    = blockIdx.y;

    const uint32_t offAq = (uint32_t)((w * 16 + (mt & 1) * 8 + l8) * QB_ROW + (mt >> 1) * 16);
    uint32_t offBk[4], offBv[8];
#pragma unroll
    for (int j = 0; j < 4; j++)
        offBk[j] = (uint32_t)((j * 16 + (mt >> 1) * 8 + l8) * KB_ROW + (mt & 1) * 16);
#pragma unroll
    for (int j = 0; j < 8; j++)
        offBv[j] = (uint32_t)((j * 16 + (mt >> 1) * 8 + l8) * VB_ROW + (mt & 1) * 16);

#pragma unroll
    for (int i = 0; i < 16; i++) {
        int e = tid + i * 256;
        int p = e >> 11;
        int r = (e >> 4) & 127;
        int c = e & 15;
        const __nv_bfloat16* s = (p ? ql : qh) + (size_t)(qbi * 128 + r) * EMB + h * HDIM + c * 8;
        cpa16(sQ + p * SM_QPL + r * QB_ROW + c * 16, s);
    }

    auto load_kv = [&](int buf, int kb) {
        uint32_t kvb = sQ + SM_Q + buf * SM_KV;
#pragma unroll
        for (int i = 0; i < 8; i++) {
            int e = tid + i * 256;
            int p = e >> 10;
            int r = (e >> 4) & 63;
            int c = e & 15;
            const __nv_bfloat16* s = (p ? kl : kh) + (size_t)(kb * 64 + r) * EMB + h * HDIM + c * 8;
            cpa16(kvb + p * SM_KPL + r * KB_ROW + c * 16, s);
        }
#pragma unroll
        for (int i = 0; i < 8; i++) {
            int e = tid + i * 256;
            int p = e >> 10;
            int r = (e >> 3) & 127;
            int c = e & 7;
            const __nv_bfloat16* s = (p ? vtl : vth) + (size_t)(h * HDIM + r) * S_LEN + kb * 64 + c * 8;
            cpa16(kvb + 2 * SM_KPL + p * SM_VPL + r * VB_ROW + c * 16, s);
        }
    };

    const int nkb = 2 * qbi + 2;
    load_kv(0, 0);
    CPA_COMMIT();

    float acco[16][4];
#pragma unroll
    for (int j = 0; j < 16; j++)
#pragma unroll
        for (int t = 0; t < 4; t++) acco[j][t] = 0.f;
    float m0 = -1e30f, m8 = -1e30f, l0 = 0.f, lsum8 = 0.f;

    const int row0 = qbi * 128 + w * 16 + g;
    const int row8 = row0 + 8;

    for (int kb = 0; kb < nkb; kb++) {
        if (kb + 1 < nkb) load_kv((kb + 1) & 1, kb + 1);
        CPA_COMMIT();
        CPA_WAIT1();
        __syncthreads();

        const uint32_t kvb = sQ + SM_Q + (kb & 1) * SM_KV;

        float accs[8][4];
#pragma unroll
        for (int j = 0; j < 8; j++)
#pragma unroll
            for (int t = 0; t < 4; t++) accs[j][t] = 0.f;

        const uint32_t qoff[3] = {0u, 0u, (uint32_t)SM_QPL};
        const uint32_t koff[3] = {0u, (uint32_t)SM_KPL, 0u};
#pragma unroll
        for (int p = 0; p < 3; p++) {
#pragma unroll
            for (int ks = 0; ks < 8; ks++) {
                uint32_t a[4];
                ldsm4(sQ + qoff[p] + offAq + ks * 32, a[0], a[1], a[2], a[3]);
#pragma unroll
                for (int j = 0; j < 4; j++) {
                    uint32_t b0, b1, b2, b3;
                    ldsm4(kvb + koff[p] + offBk[j] + ks * 32, b0, b1, b2, b3);
                    mma_bf16(accs[j * 2 + 0], a, b0, b1);
                    mma_bf16(accs[j * 2 + 1], a, b2, b3);
                }
            }
        }

        if (kb >= 2 * qbi) {
#pragma unroll
            for (int jt = 0; jt < 8; jt++) {
                int col = kb * 64 + jt * 8 + 2 * qd;
                if (col     > row0) accs[jt][0] = -1e30f;
                if (col + 1 > row0) accs[jt][1] = -1e30f;
                if (col     > row8) accs[jt][2] = -1e30f;
                if (col + 1 > row8) accs[jt][3] = -1e30f;
            }
        }

        float mx0 = -1e30f, mx8 = -1e30f;
#pragma unroll
        for (int jt = 0; jt < 8; jt++) {
            mx0 = fmaxf(mx0, fmaxf(accs[jt][0], accs[jt][1]));
            mx8 = fmaxf(mx8, fmaxf(accs[jt][2], accs[jt][3]));
        }
        mx0 = fmaxf(mx0, __shfl_xor_sync(0xffffffffu, mx0, 1));
        mx0 = fmaxf(mx0, __shfl_xor_sync(0xffffffffu, mx0, 2));
        mx8 = fmaxf(mx8, __shfl_xor_sync(0xffffffffu, mx8, 1));
        mx8 = fmaxf(mx8, __shfl_xor_sync(0xffffffffu, mx8, 2));

        float nm0 = fmaxf(m0, mx0), nm8 = fmaxf(m8, mx8);
        float al0 = __expf(m0 - nm0), al8 = __expf(m8 - nm8);
        m0 = nm0; m8 = nm8;

        float s0 = 0.f, s8 = 0.f;
#pragma unroll
        for (int jt = 0; jt < 8; jt++) {
            accs[jt][0] = __expf(accs[jt][0] - nm0);
            accs[jt][1] = __expf(accs[jt][1] - nm0);
            accs[jt][2] = __expf(accs[jt][2] - nm8);
            accs[jt][3] = __expf(accs[jt][3] - nm8);
            s0 += accs[jt][0] + accs[jt][1];
            s8 += accs[jt][2] + accs[jt][3];
        }
        s0 += __shfl_xor_sync(0xffffffffu, s0, 1);
        s0 += __shfl_xor_sync(0xffffffffu, s0, 2);
        s8 += __shfl_xor_sync(0xffffffffu, s8, 1);
        s8 += __shfl_xor_sync(0xffffffffu, s8, 2);
        l0 = l0 * al0 + s0;
        lsum8 = lsum8 * al8 + s8;

#pragma unroll
        for (int j = 0; j < 16; j++) {
            acco[j][0] *= al0; acco[j][1] *= al0;
            acco[j][2] *= al8; acco[j][3] *= al8;
        }

        uint32_t phh[8][2], pll[8][2];
#pragma unroll
        for (int jt = 0; jt < 8; jt++) {
            __nv_bfloat162 h2 = __floats2bfloat162_rn(accs[jt][0], accs[jt][1]);
            float2 hf = __bfloat1622float2(h2);
            phh[jt][0] = b2u(h2);
            pll[jt][0] = b2u(__floats2bfloat162_rn(accs[jt][0] - hf.x, accs[jt][1] - hf.y));
            h2 = __floats2bfloat162_rn(accs[jt][2], accs[jt][3]);
            hf = __bfloat1622float2(h2);
            phh[jt][1] = b2u(h2);
            pll[jt][1] = b2u(__floats2bfloat162_rn(accs[jt][2] - hf.x, accs[jt][3] - hf.y));
        }

        const uint32_t vbase = kvb + 2 * SM_KPL;
#pragma unroll
        for (int p = 0; p < 3; p++) {
            const uint32_t voff = (p == 1) ? (uint32_t)SM_VPL : 0u;
#pragma unroll
            for (int t = 0; t < 4; t++) {
                uint32_t a[4];
                if (p == 2) {
                    a[0] = pll[2 * t][0]; a[1] = pll[2 * t][1];
                    a[2] = pll[2 * t + 1][0]; a[3] = pll[2 * t + 1][1];
                } else {
                    a[0] = phh[2 * t][0]; a[1] = phh[2 * t][1];
                    a[2] = phh[2 * t + 1][0]; a[3] = phh[2 * t + 1][1];
                }
#pragma unroll
                for (int jn = 0; jn < 8; jn++) {
                    uint32_t b0, b1, b2, b3;
                    ldsm4(vbase + voff + offBv[jn] + t * 32, b0, b1, b2, b3);
                    mma_bf16(acco[jn * 2 + 0], a, b0, b1);
                    mma_bf16(acco[jn * 2 + 1], a, b2, b3);
                }
            }
        }
        __syncthreads();
    }

    float inv0 = 1.f / l0, inv8 = 1.f / lsum8;
#pragma unroll
    for (int jt = 0; jt < 16; jt++) {
        int col = h * HDIM + jt * 8 + 2 * qd;
        *(float2*)(o + (size_t)row0 * EMB + col) =
            make_float2(acco[jt][0] * inv0, acco[jt][1] * inv0);
        *(float2*)(o + (size_t)row8 * EMB + col) =
            make_float2(acco[jt][2] * inv8, acco[jt][3] * inv8);
    }
}

// ---------------- launch ----------------
extern "C" void kernel_launch(void* const* d_in, const int* in_sizes, int n_in,
                              void* d_out, int out_size)
{
    const float* x  = (const float*)d_in[0];
    const float* rc = (const float*)d_in[1];
    const float* rs = (const float*)d_in[2];
    const float* Wq = (const float*)d_in[3];
    const float* Wk = (const float*)d_in[4];
    const float* Wv = (const float*)d_in[5];
    const float* Wo = (const float*)d_in[6];
    float* out = (float*)d_out;

    float *q, *k, *v, *ao;
    cudaGetSymbolAddress((void**)&q,  g_q);
    cudaGetSymbolAddress((void**)&k,  g_k);
    cudaGetSymbolAddress((void**)&v,  g_v);
    cudaGetSymbolAddress((void**)&ao, g_ao);

    __half *px, *pao, *pwq, *pwk, *pwv, *pwo;
    cudaGetSymbolAddress((void**)&px,  g_px);
    cudaGetSymbolAddress((void**)&pao, g_pao);
    cudaGetSymbolAddress((void**)&pwq, g_pwq);
    cudaGetSymbolAddress((void**)&pwk, g_pwk);
    cudaGetSymbolAddress((void**)&pwv, g_pwv);
    cudaGetSymbolAddress((void**)&pwo, g_pwo);

    __nv_bfloat16 *qh, *ql, *kh, *kl, *vth, *vtl;
    cudaGetSymbolAddress((void**)&qh,  g_qh);
    cudaGetSymbolAddress((void**)&ql,  g_ql);
    cudaGetSymbolAddress((void**)&kh,  g_kh);
    cudaGetSymbolAddress((void**)&kl,  g_kl);
    cudaGetSymbolAddress((void**)&vth, g_vth);
    cudaGetSymbolAddress((void**)&vtl, g_vtl);

    cudaFuncSetAttribute(gemm_bulk,
                         cudaFuncAttributeMaxDynamicSharedMemorySize, GB_SMEM);
    cudaFuncSetAttribute(gemm_bulk_qkv,
                         cudaFuncAttributeMaxDynamicSharedMemorySize, GB_SMEM);
    cudaFuncSetAttribute(flash_mma,
                         cudaFuncAttributeMaxDynamicSharedMemorySize, FA_SMEM);

    // repack inputs
    conv_pack<<<S_LEN, 256>>>(x, px, 128);
    conv_pack_w4<<<dim3(EMB, 4), 256>>>(Wq, Wk, Wv, Wo, pwq, pwk, pwv, pwo);

    // fused QKV projection: 384 CTAs in one launch
    dim3 gq(EMB / 256, S_LEN / 128, 3);
    gemm_bulk_qkv<<<gq, 256, GB_SMEM>>>(px, pwq, pwk, pwv, q, k, v);

    int rope_n = S_LEN * NHEAD * (HDIM / 2);
    rope_split<<<(rope_n + 255) / 256, 256>>>(q, k, rc, rs, qh, ql, kh, kl);
    vsplit_t<<<dim3(S_LEN / 64, HDIM / 64, NHEAD), 256>>>(v, vth, vtl);

    flash_mma<<<dim3(S_LEN / 128, NHEAD), 256, FA_SMEM>>>(qh, ql, kh, kl, vth, vtl, ao);

    conv_pack<<<S_LEN, 256>>>(ao, pao, 128);
    dim3 gg(EMB / 256, S_LEN / 128);
    gemm_bulk<<<gg, 256, GB_SMEM>>>(pao, pwo, out);
}